// round 12
// baseline (speedup 1.0000x reference)
#include <cuda_runtime.h>
#include <cuda_fp16.h>
#include <math.h>

#define FULL 0xffffffffu

// ---------------- f32x2 packed-FMA helpers ----------------
__device__ __forceinline__ unsigned long long pack2(float a, float b) {
    unsigned long long r;
    asm("mov.b64 %0, {%1, %2};" : "=l"(r) : "f"(a), "f"(b));
    return r;
}
__device__ __forceinline__ float2 u2f(unsigned long long v) {
    float2 r;
    asm("mov.b64 {%0, %1}, %2;" : "=f"(r.x), "=f"(r.y) : "l"(v));
    return r;
}
__device__ __forceinline__ void fma2(unsigned long long& d, unsigned long long a, unsigned long long b) {
    asm("fma.rn.f32x2 %0, %1, %2, %0;" : "+l"(d) : "l"(a), "l"(b));
}
__device__ __forceinline__ float tanh_fast(float x) {
    float e = __expf(2.f * x);
    return (e - 1.f) / (e + 1.f);
}

// ---------------- scratch ----------------
// Value buffers carry zero-initialized guard tails so clamped (zero-weight)
// corner reads past the logical end stay finite (device globals are zero-init
// at module load and the guards are never written).
__device__ __align__(16) float  g_W512[512*128];
__device__ float                g_b512[512];
__device__ __align__(16) float  g_WcombT[512*128];
__device__ __align__(16) __half g_Wvh[114688];
__device__ __align__(16) int2   g_mdA[524288];     // per point: {base, aw/65535}
__device__ __align__(16) uint4  g_mdB[524288];     // per point: 8x u16 corner products
__device__ __align__(16) __half g_v0ph[262144*32 + 140000];
__device__ __align__(16) __half g_val1[32768*256 + 272000];
__device__ __align__(16) __half g_val2[4096*256 + 70600];
__device__ __align__(16) __half g_val3[512*256 + 19200];
__device__ __align__(16) float  g_accA[4096*256];
__device__ __align__(16) float  g_accB[4096*256];
__device__ __align__(16) float  g_outbuf[128*4096];

// ---------------- K0a: fold W512 + build WcombT ----------------
__global__ void k0a_fold(const float* __restrict__ Woff, const float* __restrict__ Wwt,
                         const float* __restrict__ Wq,
                         const float* __restrict__ boff, const float* __restrict__ bwt,
                         const float* __restrict__ Wout, const float* __restrict__ Wv0) {
    const int b = blockIdx.x;
    const int t = threadIdx.x;
    if (b < 512) {
        const int j = b;
        const float* A = (j < 384) ? (Woff + j*192) : (Wwt + (j-384)*192);
        float s = 0.f;
        for (int m = 0; m < 192; m++) s += A[m] * Wq[m*128 + t];
        g_W512[j*128 + t] = s;
        if (t == 0) g_b512[j] = (j < 384) ? boff[j] : bwt[j-384];
    } else {
        const int c = b - 512;
#pragma unroll
        for (int kk = 0; kk < 4; kk++) {
            int k = t + kk*128;
            float s;
            if (k < 256) {
                int h = k >> 5, q = k & 31;
                s = 0.f;
                for (int j = 0; j < 24; j++)
                    s += Wout[c*192 + h*24 + j] * Wv0[(h*24 + j)*32 + q];
            } else {
                int k2 = k - 256;
                int h = k2 >> 5, j = k2 & 31;
                s = (j < 24) ? Wout[c*192 + h*24 + j] : 0.f;
            }
            g_WcombT[k*128 + c] = s;
        }
    }
}

// ---------------- K0b: build fp16 value weights ----------------
__global__ void k0b_wvh(const float* __restrict__ Wv1, const float* __restrict__ Wv2,
                        const float* __restrict__ Wv3) {
    int i = blockIdx.x*128 + threadIdx.x;
    for (int idx = i; idx < 114688; idx += 8192) {
        int row, k, C;
        const float* W;
        if (idx < 16384)      { row = idx >> 6;  k = idx & 63;  C = 64;  W = Wv1; }
        else if (idx < 49152) { int d = idx - 16384; row = d >> 7; k = d & 127; C = 128; W = Wv2; }
        else                  { int d = idx - 49152; row = d >> 8; k = d & 255; C = 256; W = Wv3; }
        int h = row >> 5, j = row & 31;
        float v = (j < 24) ? W[(h*24 + j)*C + k] : 0.f;
        g_Wvh[idx] = __float2half_rn(v);
    }
}

// ---------------- K123: merged k1 (0..255) + k3 HMMA (256..839) + k2 transpose (840..2887) ----------------
#define K1PX 20
#define K1PW 516
__global__ void __launch_bounds__(256) k123_fused(const float* __restrict__ qf,
                                                  const float* __restrict__ v0,
                                                  const float* __restrict__ v1,
                                                  const float* __restrict__ v2,
                                                  const float* __restrict__ v3) {
    __shared__ __align__(16) char sm1[43264];
    const int tid = threadIdx.x;
    const int b = blockIdx.x;

    if (b >= 840) {
        // ================= k2 role: transpose v0 -> fp16 [voxel][32] =================
        float* t = (float*)sm1;   // [32][129]
        const int vb = (b - 840) * 128;
        for (int e = tid; e < 32*128; e += 256) {
            int c = e >> 7, v = e & 127;
            t[c*129 + v] = v0[c*262144 + vb + v];
        }
        __syncthreads();
        for (int e = tid; e < 512; e += 256) {
            int v = e >> 2, q = e & 3;
            union { uint4 u; __half2 h[4]; } o;
#pragma unroll
            for (int j = 0; j < 4; j++)
                o.h[j] = __floats2half2_rn(t[(q*8 + 2*j)*129 + v], t[(q*8 + 2*j + 1)*129 + v]);
            *reinterpret_cast<uint4*>(&g_v0ph[(vb + v)*32 + q*8]) = o.u;
        }
        return;
    }

    if (b < 256) {
        // ================= k1 role: 512x128 GEMM + epilogue =================
        float* xs   = (float*)sm1;            // [128][20]
        float* sW   = (float*)(sm1 + 10240);  // [16][516]
        float* sbuf = (float*)sm1;            // reuse: [512][20]

        const int nb = b * 16;
        const int rg = tid >> 2, cg = tid & 3;
        const int rbase = rg * 8, vbase = cg * 4;

        for (int e = tid; e < 128*16; e += 256) {
            int k = e >> 4, v = e & 15;
            xs[k*K1PX + v] = qf[k*4096 + nb + v];
        }
        unsigned long long acc2[8][2];
#pragma unroll
        for (int i = 0; i < 8; i++) {
            float bv = g_b512[rbase + i];
            acc2[i][0] = pack2(bv, bv);
            acc2[i][1] = acc2[i][0];
        }

        for (int kc = 0; kc < 128; kc += 16) {
            __syncthreads();
            for (int e = tid; e < 512*4; e += 256) {
                int r = e >> 2, k4 = e & 3;
                float4 w4 = *(const float4*)&g_W512[r*128 + kc + k4*4];
                sW[(k4*4+0)*K1PW + r] = w4.x;
                sW[(k4*4+1)*K1PW + r] = w4.y;
                sW[(k4*4+2)*K1PW + r] = w4.z;
                sW[(k4*4+3)*K1PW + r] = w4.w;
            }
            __syncthreads();
#pragma unroll
            for (int k = 0; k < 16; k++) {
                const float* wr = &sW[k*K1PW + rbase];
                float4 wa = *(const float4*)(wr);
                float4 wb = *(const float4*)(wr + 4);
                float w[8] = {wa.x,wa.y,wa.z,wa.w, wb.x,wb.y,wb.z,wb.w};
                ulonglong2 xv = *(const ulonglong2*)&xs[(kc + k)*K1PX + vbase];
#pragma unroll
                for (int i = 0; i < 8; i++) {
                    unsigned long long wp = pack2(w[i], w[i]);
                    fma2(acc2[i][0], wp, xv.x);
                    fma2(acc2[i][1], wp, xv.y);
                }
            }
        }
        __syncthreads();
#pragma unroll
        for (int i = 0; i < 8; i++) {
            float2 lo = u2f(acc2[i][0]), hi = u2f(acc2[i][1]);
            *(float4*)&sbuf[(rbase + i)*K1PX + vbase] = make_float4(lo.x, lo.y, hi.x, hi.y);
        }
        __syncthreads();

        // epilogue: unit u = (h,v); each thread handles 2 scales (8 points)
        const int u = tid >> 1;
        const int h = u >> 4, v = u & 15;
        const int n = nb + v;
        const int wq = n & 15, hq = (n >> 4) & 15, dq = n >> 8;
        const float bgx = -1.f + (float)wq * (2.f/15.f);
        const float bgy = -1.f + (float)hq * (2.f/15.f);
        const float bgz = -1.f + (float)dq * (2.f/15.f);
        float e[16];
        float m = -1e30f;
#pragma unroll
        for (int j = 0; j < 16; j++) {
            e[j] = sbuf[(384 + h*16 + j)*K1PX + v];
            m = fmaxf(m, e[j]);
        }
        float sum = 0.f;
#pragma unroll
        for (int j = 0; j < 16; j++) { e[j] = __expf(e[j] - m); sum += e[j]; }
        const float inv = 1.f / sum;
        const int sb = (tid & 1) * 2;
#pragma unroll
        for (int si = 0; si < 2; si++) {
            const int s = sb + si;
            const int S = 64 >> s;
            const float fS = (float)S;
            const int stride = (s == 0) ? 32 : 256;
            const int hofs = (s == 0) ? 0 : h*32;
#pragma unroll
            for (int p = 0; p < 4; p++) {
                const int rb = ((h*4 + s)*4 + p) * 3;
                float gx = bgx + tanh_fast(sbuf[(rb+0)*K1PX + v]) * 0.35f;
                float gy = bgy + tanh_fast(sbuf[(rb+1)*K1PX + v]) * 0.35f;
                float gz = bgz + tanh_fast(sbuf[(rb+2)*K1PX + v]) * 0.35f;
                float ix = fminf(fmaxf(((gx + 1.f)*fS - 1.f)*0.5f, 0.f), fS - 1.f);
                float iy = fminf(fmaxf(((gy + 1.f)*fS - 1.f)*0.5f, 0.f), fS - 1.f);
                float iz = fminf(fmaxf(((gz + 1.f)*fS - 1.f)*0.5f, 0.f), fS - 1.f);
                float x0f = floorf(ix), y0f = floorf(iy), z0f = floorf(iz);
                float wx = ix - x0f, wy = iy - y0f, wz = iz - z0f;
                int x0 = (int)x0f, y0 = (int)y0f, z0 = (int)z0f;
                int base = ((z0*S + y0)*S + x0)*stride + hofs;
                float aw = e[s*4 + p] * inv;
                float wx1 = 1.f - wx, wy1 = 1.f - wy, wz1 = 1.f - wz;
                float p00 = wz1*wy1, p01 = wz1*wy, p10 = wz*wy1, p11 = wz*wy;
                unsigned u0 = (unsigned)(p00*wx1*65535.f + 0.5f);
                unsigned u1 = (unsigned)(p00*wx *65535.f + 0.5f);
                unsigned u2 = (unsigned)(p01*wx1*65535.f + 0.5f);
                unsigned u3 = (unsigned)(p01*wx *65535.f + 0.5f);
                unsigned u4 = (unsigned)(p10*wx1*65535.f + 0.5f);
                unsigned u5 = (unsigned)(p10*wx *65535.f + 0.5f);
                unsigned u6 = (unsigned)(p11*wx1*65535.f + 0.5f);
                unsigned u7 = (unsigned)(p11*wx *65535.f + 0.5f);
                uint4 B = make_uint4((u1<<16)|u0, (u3<<16)|u2, (u5<<16)|u4, (u7<<16)|u6);
                int2 A = make_int2(base, __float_as_int(aw * (1.f/65535.f)));
                int idx = (h*16 + s*4 + p)*4096 + n;
                g_mdA[idx] = A;
                g_mdB[idx] = B;
            }
        }
        return;
    }

    // ================= k3 role: HMMA projections scales 1..3 =================
    const int b2 = b - 256;
    const float* vsrc; const __half* Wg; __half* outv;
    int C, Nv, nb;
    if (b2 < 512)      { vsrc = v1; Wg = g_Wvh;         outv = g_val1; C = 64;  Nv = 32768; nb = b2*64; }
    else if (b2 < 576) { vsrc = v2; Wg = g_Wvh + 16384; outv = g_val2; C = 128; Nv = 4096;  nb = (b2-512)*64; }
    else               { vsrc = v3; Wg = g_Wvh + 49152; outv = g_val3; C = 256; Nv = 512;   nb = (b2-576)*64; }

    __half* Xt = (__half*)sm1;     // [64][18]
    __half* Ds = (__half*)sm1;     // reuse: [64][264]

    const int warp = tid >> 5, lane = tid & 31;
    const int grp = lane >> 2, tg = lane & 3;
    const int wbase = warp * 32;

    float acc[2][8][4];
#pragma unroll
    for (int mt = 0; mt < 2; mt++)
#pragma unroll
        for (int nt = 0; nt < 8; nt++)
#pragma unroll
            for (int i = 0; i < 4; i++) acc[mt][nt][i] = 0.f;

    const int xk = tid >> 4, xv = (tid & 15) * 4;

    for (int kc = 0; kc < C; kc += 16) {
        float4 x4 = *(const float4*)&vsrc[(size_t)(kc + xk)*Nv + nb + xv];
        Xt[(xv+0)*18 + xk] = __float2half_rn(x4.x);
        Xt[(xv+1)*18 + xk] = __float2half_rn(x4.y);
        Xt[(xv+2)*18 + xk] = __float2half_rn(x4.z);
        Xt[(xv+3)*18 + xk] = __float2half_rn(x4.w);
        __syncthreads();

        unsigned af[2][4];
#pragma unroll
        for (int mt = 0; mt < 2; mt++) {
            const __half* Ar = Wg + (size_t)(wbase + mt*16 + grp)*C + kc;
            af[mt][0] = *(const unsigned*)(Ar + 2*tg);
            af[mt][1] = *(const unsigned*)(Ar + 8*C + 2*tg);
            af[mt][2] = *(const unsigned*)(Ar + 2*tg + 8);
            af[mt][3] = *(const unsigned*)(Ar + 8*C + 2*tg + 8);
        }
#pragma unroll
        for (int nt = 0; nt < 8; nt++) {
            const __half* Br = Xt + (nt*8 + grp)*18 + 2*tg;
            unsigned b0 = *(const unsigned*)Br;
            unsigned b1 = *(const unsigned*)(Br + 8);
#pragma unroll
            for (int mt = 0; mt < 2; mt++) {
                asm volatile(
                    "mma.sync.aligned.m16n8k16.row.col.f32.f16.f16.f32 "
                    "{%0,%1,%2,%3}, {%4,%5,%6,%7}, {%8,%9}, {%0,%1,%2,%3};"
                    : "+f"(acc[mt][nt][0]), "+f"(acc[mt][nt][1]),
                      "+f"(acc[mt][nt][2]), "+f"(acc[mt][nt][3])
                    : "r"(af[mt][0]), "r"(af[mt][1]), "r"(af[mt][2]), "r"(af[mt][3]),
                      "r"(b0), "r"(b1));
            }
        }
        __syncthreads();
    }

#pragma unroll
    for (int mt = 0; mt < 2; mt++) {
        const int slot = wbase + mt*16 + grp;
#pragma unroll
        for (int nt = 0; nt < 8; nt++) {
            const int vv = nt*8 + 2*tg;
            Ds[vv*264 + slot]         = __float2half_rn(acc[mt][nt][0]);
            Ds[(vv+1)*264 + slot]     = __float2half_rn(acc[mt][nt][1]);
            Ds[vv*264 + slot + 8]     = __float2half_rn(acc[mt][nt][2]);
            Ds[(vv+1)*264 + slot + 8] = __float2half_rn(acc[mt][nt][3]);
        }
    }
    __syncthreads();
    for (int i = tid; i < 2048; i += 256) {
        int v = i >> 5, j = i & 31;
        *reinterpret_cast<uint4*>(&outv[(size_t)(nb + v)*256 + j*8]) =
            *reinterpret_cast<const uint4*>(&Ds[v*264 + j*8]);
    }
}

// ---------------- K4: gather, guard-based (no border decode) ----------------
__global__ void __launch_bounds__(512, 3) k4_sample() {
    const int tid = threadIdx.x;
    const int warp = tid >> 5, lane = tid & 31;
    const int gw = blockIdx.x*16 + warp;
    const int h = gw >> 12, n = gw & 4095;
    const int corner = lane >> 2, q8 = (lane & 3) * 8;
    const int cx = corner & 1, cy = (corner >> 1) & 1, cz = corner >> 2;

    float2 acc0[4], acc1[4];
#pragma unroll
    for (int j = 0; j < 4; j++) { acc0[j] = make_float2(0.f,0.f); acc1[j] = make_float2(0.f,0.f); }

    const int ptb = h*16*4096 + n;
    const unsigned short* mdw = reinterpret_cast<const unsigned short*>(g_mdB);

    // scale 0: stride 32, S=64
    {
        const int cq = q8 + (cx ? 32 : 0) + (cy ? 64*32 : 0) + (cz ? 64*64*32 : 0);
#pragma unroll
        for (int p = 0; p < 4; p++) {
            int idx = ptb + p*4096;
            int2 A = g_mdA[idx];
            float w = (float)mdw[idx*8 + corner] * __int_as_float(A.y);
            union { uint4 u; __half2 hh[4]; } d;
            d.u = *reinterpret_cast<const uint4*>(g_v0ph + A.x + cq);
#pragma unroll
            for (int j = 0; j < 4; j++) {
                float2 f = __half22float2(d.hh[j]);
                acc0[j].x += w*f.x; acc0[j].y += w*f.y;
            }
        }
    }
    // scales 1..3: stride 256
#pragma unroll
    for (int s = 1; s < 4; s++) {
        const __half* vptr = (s == 1) ? g_val1 : (s == 2) ? g_val2 : g_val3;
        const int S = 64 >> s;
        const int cq = q8 + (cx ? 256 : 0) + (cy ? S*256 : 0) + (cz ? S*S*256 : 0);
#pragma unroll
        for (int p = 0; p < 4; p++) {
            int idx = ptb + (s*4 + p)*4096;
            int2 A = g_mdA[idx];
            float w = (float)mdw[idx*8 + corner] * __int_as_float(A.y);
            union { uint4 u; __half2 hh[4]; } d;
            d.u = *reinterpret_cast<const uint4*>(vptr + A.x + cq);
#pragma unroll
            for (int j = 0; j < 4; j++) {
                float2 f = __half22float2(d.hh[j]);
                acc1[j].x += w*f.x; acc1[j].y += w*f.y;
            }
        }
    }
#pragma unroll
    for (int m = 4; m <= 16; m <<= 1) {
#pragma unroll
        for (int j = 0; j < 4; j++) {
            acc0[j].x += __shfl_xor_sync(FULL, acc0[j].x, m);
            acc0[j].y += __shfl_xor_sync(FULL, acc0[j].y, m);
            acc1[j].x += __shfl_xor_sync(FULL, acc1[j].x, m);
            acc1[j].y += __shfl_xor_sync(FULL, acc1[j].y, m);
        }
    }
    if (lane < 4) {
        const int base = n*256 + h*32 + q8;
        *(float4*)&g_accA[base]     = make_float4(acc0[0].x, acc0[0].y, acc0[1].x, acc0[1].y);
        *(float4*)&g_accA[base + 4] = make_float4(acc0[2].x, acc0[2].y, acc0[3].x, acc0[3].y);
        *(float4*)&g_accB[base]     = make_float4(acc1[0].x, acc1[0].y, acc1[1].x, acc1[1].y);
        *(float4*)&g_accB[base + 4] = make_float4(acc1[2].x, acc1[2].y, acc1[3].x, acc1[3].y);
    }
}

// ---------------- K5: combined output GEMM [128][512] @ [512][4096], N-tile 32, grid 128 ----------------
#define K5PX 36
#define K5PW 132
__global__ void __launch_bounds__(256) k5_out() {
    __shared__ __align__(16) float xs[32*K5PX];
    __shared__ __align__(16) float sW[32*K5PW];
    const int tid = threadIdx.x;
    const int nb = blockIdx.x * 32;
    const int rg = tid >> 4, cg = tid & 15;
    const int rbase = rg * 8;
    const int lv = tid >> 3, lk = (tid & 7) * 4;

    unsigned long long acc2[8];
#pragma unroll
    for (int i = 0; i < 8; i++) acc2[i] = 0ull;

    for (int kc = 0; kc < 512; kc += 32) {
        __syncthreads();
        {
            const float* srcbuf = (kc < 256) ? g_accA : g_accB;
            const int ko = kc & 255;
            float4 x4 = *(const float4*)&srcbuf[(nb + lv)*256 + ko + lk];
            xs[(lk+0)*K5PX + lv] = x4.x;
            xs[(lk+1)*K5PX + lv] = x4.y;
            xs[(lk+2)*K5PX + lv] = x4.z;
            xs[(lk+3)*K5PX + lv] = x4.w;
        }
        for (int e = tid; e < 32*32; e += 256) {
            int k = e >> 5, c4 = e & 31;
            *(float4*)&sW[k*K5PW + c4*4] = *(const float4*)&g_WcombT[(kc + k)*128 + c4*4];
        }
        __syncthreads();
#pragma unroll
        for (int k = 0; k < 32; k++) {
            const float* wr = &sW[k*K5PW + rbase];
            float4 wa = *(const float4*)(wr);
            float4 wb = *(const float4*)(wr + 4);
            float w[8] = {wa.x, wa.y, wa.z, wa.w, wb.x, wb.y, wb.z, wb.w};
            unsigned long long xv = *(const unsigned long long*)&xs[k*K5PX + cg*2];
#pragma unroll
            for (int i = 0; i < 8; i++) {
                unsigned long long wp = pack2(w[i], w[i]);
                fma2(acc2[i], wp, xv);
            }
        }
    }
#pragma unroll
    for (int i = 0; i < 8; i++) {
        float2 f = u2f(acc2[i]);
        *(float2*)&g_outbuf[(rbase + i)*4096 + nb + cg*2] = f;
    }
}

// ---------------- K6: InstanceNorm per channel ----------------
__global__ void __launch_bounds__(256) k6_norm(const float* __restrict__ gamma,
                                               const float* __restrict__ beta,
                                               float* __restrict__ out) {
    const int c = blockIdx.x, tid = threadIdx.x;
    const float* row = &g_outbuf[c*4096];
    float s = 0.f, s2 = 0.f;
    for (int i = tid; i < 4096; i += 256) { float x = row[i]; s += x; s2 += x*x; }
#pragma unroll
    for (int m = 16; m > 0; m >>= 1) {
        s  += __shfl_xor_sync(FULL, s,  m);
        s2 += __shfl_xor_sync(FULL, s2, m);
    }
    __shared__ float rs[8], rq[8];
    __shared__ float smu, srstd;
    if ((tid & 31) == 0) { rs[tid >> 5] = s; rq[tid >> 5] = s2; }
    __syncthreads();
    if (tid == 0) {
        float ts = 0.f, tq = 0.f;
        for (int i = 0; i < 8; i++) { ts += rs[i]; tq += rq[i]; }
        float mu = ts * (1.f/4096.f);
        smu = mu;
        srstd = rsqrtf(tq * (1.f/4096.f) - mu*mu + 1e-5f);
    }
    __syncthreads();
    const float g = gamma[c] * srstd, b = beta[c], mu = smu;
    for (int i = tid; i < 4096; i += 256)
        out[c*4096 + i] = (row[i] - mu) * g + b;
}

// ---------------- launch ----------------
extern "C" void kernel_launch(void* const* d_in, const int* in_sizes, int n_in,
                              void* d_out, int out_size) {
    const float* qf    = (const float*)d_in[0];
    const float* v0    = (const float*)d_in[1];
    const float* v1    = (const float*)d_in[2];
    const float* v2    = (const float*)d_in[3];
    const float* v3    = (const float*)d_in[4];
    const float* Wq    = (const float*)d_in[5];
    const float* Wv0   = (const float*)d_in[6];
    const float* Wv1   = (const float*)d_in[7];
    const float* Wv2   = (const float*)d_in[8];
    const float* Wv3   = (const float*)d_in[9];
    const float* Woff  = (const float*)d_in[10];
    const float* boff  = (const float*)d_in[11];
    const float* Wwt   = (const float*)d_in[12];
    const float* bwt   = (const float*)d_in[13];
    const float* Wout  = (const float*)d_in[14];
    const float* gamma = (const float*)d_in[15];
    const float* beta  = (const float*)d_in[16];
    float* out = (float*)d_out;

    // Order: ncu's captured launch (#4) is the guard-based k4_sample.
    k0a_fold<<<640, 128>>>(Woff, Wwt, Wq, boff, bwt, Wout, Wv0);
    k0b_wvh<<<64, 128>>>(Wv1, Wv2, Wv3);
    k123_fused<<<2888, 256>>>(qf, v0, v1, v2, v3);
    k4_sample<<<2048, 512>>>();
    k5_out<<<128, 256>>>();
    k6_norm<<<128, 256>>>(gamma, beta, out);
}

// round 13
// speedup vs baseline: 1.1657x; 1.1657x over previous
#include <cuda_runtime.h>
#include <cuda_fp16.h>
#include <math.h>

#define FULL 0xffffffffu

// ---------------- f32x2 packed-FMA helpers ----------------
__device__ __forceinline__ unsigned long long pack2(float a, float b) {
    unsigned long long r;
    asm("mov.b64 %0, {%1, %2};" : "=l"(r) : "f"(a), "f"(b));
    return r;
}
__device__ __forceinline__ float2 u2f(unsigned long long v) {
    float2 r;
    asm("mov.b64 {%0, %1}, %2;" : "=f"(r.x), "=f"(r.y) : "l"(v));
    return r;
}
__device__ __forceinline__ void fma2(unsigned long long& d, unsigned long long a, unsigned long long b) {
    asm("fma.rn.f32x2 %0, %1, %2, %0;" : "+l"(d) : "l"(a), "l"(b));
}
__device__ __forceinline__ float tanh_fast(float x) {
    float e = __expf(2.f * x);
    return (e - 1.f) / (e + 1.f);
}

// ---------------- scratch ----------------
// Value buffers carry zero-initialized guard tails so clamped (zero-weight)
// corner reads past the logical end stay finite.
__device__ __align__(16) float  g_W512[512*128];
__device__ float                g_b512[512];
__device__ __align__(16) float  g_WcombT[512*128];
__device__ __align__(16) __half g_Wvh[114688];
__device__ __align__(16) int2   g_mdA[524288];     // per point: {base, aw/65535}
__device__ __align__(16) uint4  g_mdB[524288];     // per point: 8x u16 corner products
__device__ __align__(16) __half g_v0ph[262144*32 + 140000];
__device__ __align__(16) __half g_val1[32768*256 + 272000];
__device__ __align__(16) __half g_val2[4096*256 + 70600];
__device__ __align__(16) __half g_val3[512*256 + 19200];
__device__ __align__(16) float  g_accA[4096*256];
__device__ __align__(16) float  g_accB[4096*256];
__device__ __align__(16) float  g_outbuf[128*4096];

// ---------------- K0a: fold W512 + build WcombT ----------------
__global__ void k0a_fold(const float* __restrict__ Woff, const float* __restrict__ Wwt,
                         const float* __restrict__ Wq,
                         const float* __restrict__ boff, const float* __restrict__ bwt,
                         const float* __restrict__ Wout, const float* __restrict__ Wv0) {
    const int b = blockIdx.x;
    const int t = threadIdx.x;
    if (b < 512) {
        const int j = b;
        const float* A = (j < 384) ? (Woff + j*192) : (Wwt + (j-384)*192);
        float s = 0.f;
        for (int m = 0; m < 192; m++) s += A[m] * Wq[m*128 + t];
        g_W512[j*128 + t] = s;
        if (t == 0) g_b512[j] = (j < 384) ? boff[j] : bwt[j-384];
    } else {
        const int c = b - 512;
#pragma unroll
        for (int kk = 0; kk < 4; kk++) {
            int k = t + kk*128;
            float s;
            if (k < 256) {
                int h = k >> 5, q = k & 31;
                s = 0.f;
                for (int j = 0; j < 24; j++)
                    s += Wout[c*192 + h*24 + j] * Wv0[(h*24 + j)*32 + q];
            } else {
                int k2 = k - 256;
                int h = k2 >> 5, j = k2 & 31;
                s = (j < 24) ? Wout[c*192 + h*24 + j] : 0.f;
            }
            g_WcombT[k*128 + c] = s;
        }
    }
}

// ---------------- K0b: build fp16 value weights ----------------
__global__ void k0b_wvh(const float* __restrict__ Wv1, const float* __restrict__ Wv2,
                        const float* __restrict__ Wv3) {
    int i = blockIdx.x*128 + threadIdx.x;
    for (int idx = i; idx < 114688; idx += 8192) {
        int row, k, C;
        const float* W;
        if (idx < 16384)      { row = idx >> 6;  k = idx & 63;  C = 64;  W = Wv1; }
        else if (idx < 49152) { int d = idx - 16384; row = d >> 7; k = d & 127; C = 128; W = Wv2; }
        else                  { int d = idx - 49152; row = d >> 8; k = d & 255; C = 256; W = Wv3; }
        int h = row >> 5, j = row & 31;
        float v = (j < 24) ? W[(h*24 + j)*C + k] : 0.f;
        g_Wvh[idx] = __float2half_rn(v);
    }
}

// ---------------- K2: transpose v0 -> fp16 [voxel][32] (standalone: high residency) ----------------
__global__ void __launch_bounds__(256) k2_packv0(const float* __restrict__ v0) {
    __shared__ float t[32*129];
    const int vb = blockIdx.x * 128;
    const int tid = threadIdx.x;
    for (int e = tid; e < 32*128; e += 256) {
        int c = e >> 7, v = e & 127;
        t[c*129 + v] = v0[c*262144 + vb + v];
    }
    __syncthreads();
    for (int e = tid; e < 512; e += 256) {
        int v = e >> 2, q = e & 3;
        union { uint4 u; __half2 h[4]; } o;
#pragma unroll
        for (int j = 0; j < 4; j++)
            o.h[j] = __floats2half2_rn(t[(q*8 + 2*j)*129 + v], t[(q*8 + 2*j + 1)*129 + v]);
        *reinterpret_cast<uint4*>(&g_v0ph[(vb + v)*32 + q*8]) = o.u;
    }
}

// ---------------- K13: merged k1 (blocks 0..255) + k3 HMMA (blocks 256..839) ----------------
#define K1PX 20
#define K1PW 516
__global__ void __launch_bounds__(256) k13_fused(const float* __restrict__ qf,
                                                 const float* __restrict__ v1,
                                                 const float* __restrict__ v2,
                                                 const float* __restrict__ v3) {
    __shared__ __align__(16) char sm1[43264];
    const int tid = threadIdx.x;
    const int b = blockIdx.x;

    if (b < 256) {
        // ================= k1 role: 512x128 GEMM + epilogue =================
        float* xs   = (float*)sm1;            // [128][20]
        float* sW   = (float*)(sm1 + 10240);  // [16][516]
        float* sbuf = (float*)sm1;            // reuse: [512][20]

        const int nb = b * 16;
        const int rg = tid >> 2, cg = tid & 3;
        const int rbase = rg * 8, vbase = cg * 4;

        for (int e = tid; e < 128*16; e += 256) {
            int k = e >> 4, v = e & 15;
            xs[k*K1PX + v] = qf[k*4096 + nb + v];
        }
        unsigned long long acc2[8][2];
#pragma unroll
        for (int i = 0; i < 8; i++) {
            float bv = g_b512[rbase + i];
            acc2[i][0] = pack2(bv, bv);
            acc2[i][1] = acc2[i][0];
        }

        for (int kc = 0; kc < 128; kc += 16) {
            __syncthreads();
            for (int e = tid; e < 512*4; e += 256) {
                int r = e >> 2, k4 = e & 3;
                float4 w4 = *(const float4*)&g_W512[r*128 + kc + k4*4];
                sW[(k4*4+0)*K1PW + r] = w4.x;
                sW[(k4*4+1)*K1PW + r] = w4.y;
                sW[(k4*4+2)*K1PW + r] = w4.z;
                sW[(k4*4+3)*K1PW + r] = w4.w;
            }
            __syncthreads();
#pragma unroll
            for (int k = 0; k < 16; k++) {
                const float* wr = &sW[k*K1PW + rbase];
                float4 wa = *(const float4*)(wr);
                float4 wb = *(const float4*)(wr + 4);
                float w[8] = {wa.x,wa.y,wa.z,wa.w, wb.x,wb.y,wb.z,wb.w};
                ulonglong2 xv = *(const ulonglong2*)&xs[(kc + k)*K1PX + vbase];
#pragma unroll
                for (int i = 0; i < 8; i++) {
                    unsigned long long wp = pack2(w[i], w[i]);
                    fma2(acc2[i][0], wp, xv.x);
                    fma2(acc2[i][1], wp, xv.y);
                }
            }
        }
        __syncthreads();
#pragma unroll
        for (int i = 0; i < 8; i++) {
            float2 lo = u2f(acc2[i][0]), hi = u2f(acc2[i][1]);
            *(float4*)&sbuf[(rbase + i)*K1PX + vbase] = make_float4(lo.x, lo.y, hi.x, hi.y);
        }
        __syncthreads();

        // epilogue: unit u = (h,v); each thread handles 2 scales (8 points)
        const int u = tid >> 1;
        const int h = u >> 4, v = u & 15;
        const int n = nb + v;
        const int wq = n & 15, hq = (n >> 4) & 15, dq = n >> 8;
        const float bgx = -1.f + (float)wq * (2.f/15.f);
        const float bgy = -1.f + (float)hq * (2.f/15.f);
        const float bgz = -1.f + (float)dq * (2.f/15.f);
        float e[16];
        float m = -1e30f;
#pragma unroll
        for (int j = 0; j < 16; j++) {
            e[j] = sbuf[(384 + h*16 + j)*K1PX + v];
            m = fmaxf(m, e[j]);
        }
        float sum = 0.f;
#pragma unroll
        for (int j = 0; j < 16; j++) { e[j] = __expf(e[j] - m); sum += e[j]; }
        const float inv = 1.f / sum;
        const int sb = (tid & 1) * 2;
#pragma unroll
        for (int si = 0; si < 2; si++) {
            const int s = sb + si;
            const int S = 64 >> s;
            const float fS = (float)S;
            const int stride = (s == 0) ? 32 : 256;
            const int hofs = (s == 0) ? 0 : h*32;
#pragma unroll
            for (int p = 0; p < 4; p++) {
                const int rb = ((h*4 + s)*4 + p) * 3;
                float gx = bgx + tanh_fast(sbuf[(rb+0)*K1PX + v]) * 0.35f;
                float gy = bgy + tanh_fast(sbuf[(rb+1)*K1PX + v]) * 0.35f;
                float gz = bgz + tanh_fast(sbuf[(rb+2)*K1PX + v]) * 0.35f;
                float ix = fminf(fmaxf(((gx + 1.f)*fS - 1.f)*0.5f, 0.f), fS - 1.f);
                float iy = fminf(fmaxf(((gy + 1.f)*fS - 1.f)*0.5f, 0.f), fS - 1.f);
                float iz = fminf(fmaxf(((gz + 1.f)*fS - 1.f)*0.5f, 0.f), fS - 1.f);
                float x0f = floorf(ix), y0f = floorf(iy), z0f = floorf(iz);
                float wx = ix - x0f, wy = iy - y0f, wz = iz - z0f;
                int x0 = (int)x0f, y0 = (int)y0f, z0 = (int)z0f;
                int base = ((z0*S + y0)*S + x0)*stride + hofs;
                float aw = e[s*4 + p] * inv;
                float wx1 = 1.f - wx, wy1 = 1.f - wy, wz1 = 1.f - wz;
                float p00 = wz1*wy1, p01 = wz1*wy, p10 = wz*wy1, p11 = wz*wy;
                unsigned u0 = (unsigned)(p00*wx1*65535.f + 0.5f);
                unsigned u1 = (unsigned)(p00*wx *65535.f + 0.5f);
                unsigned u2 = (unsigned)(p01*wx1*65535.f + 0.5f);
                unsigned u3 = (unsigned)(p01*wx *65535.f + 0.5f);
                unsigned u4 = (unsigned)(p10*wx1*65535.f + 0.5f);
                unsigned u5 = (unsigned)(p10*wx *65535.f + 0.5f);
                unsigned u6 = (unsigned)(p11*wx1*65535.f + 0.5f);
                unsigned u7 = (unsigned)(p11*wx *65535.f + 0.5f);
                uint4 B = make_uint4((u1<<16)|u0, (u3<<16)|u2, (u5<<16)|u4, (u7<<16)|u6);
                int2 A = make_int2(base, __float_as_int(aw * (1.f/65535.f)));
                int idx = (h*16 + s*4 + p)*4096 + n;
                g_mdA[idx] = A;
                g_mdB[idx] = B;
            }
        }
        return;
    }

    // ================= k3 role: HMMA projections scales 1..3 =================
    const int b2 = b - 256;
    const float* vsrc; const __half* Wg; __half* outv;
    int C, Nv, nb;
    if (b2 < 512)      { vsrc = v1; Wg = g_Wvh;         outv = g_val1; C = 64;  Nv = 32768; nb = b2*64; }
    else if (b2 < 576) { vsrc = v2; Wg = g_Wvh + 16384; outv = g_val2; C = 128; Nv = 4096;  nb = (b2-512)*64; }
    else               { vsrc = v3; Wg = g_Wvh + 49152; outv = g_val3; C = 256; Nv = 512;   nb = (b2-576)*64; }

    __half* Xt = (__half*)sm1;     // [64][18]
    __half* Ds = (__half*)sm1;     // reuse: [64][264]

    const int warp = tid >> 5, lane = tid & 31;
    const int grp = lane >> 2, tg = lane & 3;
    const int wbase = warp * 32;

    float acc[2][8][4];
#pragma unroll
    for (int mt = 0; mt < 2; mt++)
#pragma unroll
        for (int nt = 0; nt < 8; nt++)
#pragma unroll
            for (int i = 0; i < 4; i++) acc[mt][nt][i] = 0.f;

    const int xk = tid >> 4, xv = (tid & 15) * 4;

    for (int kc = 0; kc < C; kc += 16) {
        float4 x4 = *(const float4*)&vsrc[(size_t)(kc + xk)*Nv + nb + xv];
        Xt[(xv+0)*18 + xk] = __float2half_rn(x4.x);
        Xt[(xv+1)*18 + xk] = __float2half_rn(x4.y);
        Xt[(xv+2)*18 + xk] = __float2half_rn(x4.z);
        Xt[(xv+3)*18 + xk] = __float2half_rn(x4.w);
        __syncthreads();

        unsigned af[2][4];
#pragma unroll
        for (int mt = 0; mt < 2; mt++) {
            const __half* Ar = Wg + (size_t)(wbase + mt*16 + grp)*C + kc;
            af[mt][0] = *(const unsigned*)(Ar + 2*tg);
            af[mt][1] = *(const unsigned*)(Ar + 8*C + 2*tg);
            af[mt][2] = *(const unsigned*)(Ar + 2*tg + 8);
            af[mt][3] = *(const unsigned*)(Ar + 8*C + 2*tg + 8);
        }
#pragma unroll
        for (int nt = 0; nt < 8; nt++) {
            const __half* Br = Xt + (nt*8 + grp)*18 + 2*tg;
            unsigned b0 = *(const unsigned*)Br;
            unsigned b1 = *(const unsigned*)(Br + 8);
#pragma unroll
            for (int mt = 0; mt < 2; mt++) {
                asm volatile(
                    "mma.sync.aligned.m16n8k16.row.col.f32.f16.f16.f32 "
                    "{%0,%1,%2,%3}, {%4,%5,%6,%7}, {%8,%9}, {%0,%1,%2,%3};"
                    : "+f"(acc[mt][nt][0]), "+f"(acc[mt][nt][1]),
                      "+f"(acc[mt][nt][2]), "+f"(acc[mt][nt][3])
                    : "r"(af[mt][0]), "r"(af[mt][1]), "r"(af[mt][2]), "r"(af[mt][3]),
                      "r"(b0), "r"(b1));
            }
        }
        __syncthreads();
    }

#pragma unroll
    for (int mt = 0; mt < 2; mt++) {
        const int slot = wbase + mt*16 + grp;
#pragma unroll
        for (int nt = 0; nt < 8; nt++) {
            const int vv = nt*8 + 2*tg;
            Ds[vv*264 + slot]         = __float2half_rn(acc[mt][nt][0]);
            Ds[(vv+1)*264 + slot]     = __float2half_rn(acc[mt][nt][1]);
            Ds[vv*264 + slot + 8]     = __float2half_rn(acc[mt][nt][2]);
            Ds[(vv+1)*264 + slot + 8] = __float2half_rn(acc[mt][nt][3]);
        }
    }
    __syncthreads();
    for (int i = tid; i < 2048; i += 256) {
        int v = i >> 5, j = i & 31;
        *reinterpret_cast<uint4*>(&outv[(size_t)(nb + v)*256 + j*8]) =
            *reinterpret_cast<const uint4*>(&Ds[v*264 + j*8]);
    }
}

// ---------------- K4: gather, guard-based (no border decode) ----------------
__global__ void __launch_bounds__(512, 3) k4_sample() {
    const int tid = threadIdx.x;
    const int warp = tid >> 5, lane = tid & 31;
    const int gw = blockIdx.x*16 + warp;
    const int h = gw >> 12, n = gw & 4095;
    const int corner = lane >> 2, q8 = (lane & 3) * 8;
    const int cx = corner & 1, cy = (corner >> 1) & 1, cz = corner >> 2;

    float2 acc0[4], acc1[4];
#pragma unroll
    for (int j = 0; j < 4; j++) { acc0[j] = make_float2(0.f,0.f); acc1[j] = make_float2(0.f,0.f); }

    const int ptb = h*16*4096 + n;
    const unsigned short* mdw = reinterpret_cast<const unsigned short*>(g_mdB);

    // scale 0: stride 32, S=64
    {
        const int cq = q8 + (cx ? 32 : 0) + (cy ? 64*32 : 0) + (cz ? 64*64*32 : 0);
#pragma unroll
        for (int p = 0; p < 4; p++) {
            int idx = ptb + p*4096;
            int2 A = g_mdA[idx];
            float w = (float)mdw[idx*8 + corner] * __int_as_float(A.y);
            union { uint4 u; __half2 hh[4]; } d;
            d.u = *reinterpret_cast<const uint4*>(g_v0ph + A.x + cq);
#pragma unroll
            for (int j = 0; j < 4; j++) {
                float2 f = __half22float2(d.hh[j]);
                acc0[j].x += w*f.x; acc0[j].y += w*f.y;
            }
        }
    }
    // scales 1..3: stride 256
#pragma unroll
    for (int s = 1; s < 4; s++) {
        const __half* vptr = (s == 1) ? g_val1 : (s == 2) ? g_val2 : g_val3;
        const int S = 64 >> s;
        const int cq = q8 + (cx ? 256 : 0) + (cy ? S*256 : 0) + (cz ? S*S*256 : 0);
#pragma unroll
        for (int p = 0; p < 4; p++) {
            int idx = ptb + (s*4 + p)*4096;
            int2 A = g_mdA[idx];
            float w = (float)mdw[idx*8 + corner] * __int_as_float(A.y);
            union { uint4 u; __half2 hh[4]; } d;
            d.u = *reinterpret_cast<const uint4*>(vptr + A.x + cq);
#pragma unroll
            for (int j = 0; j < 4; j++) {
                float2 f = __half22float2(d.hh[j]);
                acc1[j].x += w*f.x; acc1[j].y += w*f.y;
            }
        }
    }
#pragma unroll
    for (int m = 4; m <= 16; m <<= 1) {
#pragma unroll
        for (int j = 0; j < 4; j++) {
            acc0[j].x += __shfl_xor_sync(FULL, acc0[j].x, m);
            acc0[j].y += __shfl_xor_sync(FULL, acc0[j].y, m);
            acc1[j].x += __shfl_xor_sync(FULL, acc1[j].x, m);
            acc1[j].y += __shfl_xor_sync(FULL, acc1[j].y, m);
        }
    }
    if (lane < 4) {
        const int base = n*256 + h*32 + q8;
        *(float4*)&g_accA[base]     = make_float4(acc0[0].x, acc0[0].y, acc0[1].x, acc0[1].y);
        *(float4*)&g_accA[base + 4] = make_float4(acc0[2].x, acc0[2].y, acc0[3].x, acc0[3].y);
        *(float4*)&g_accB[base]     = make_float4(acc1[0].x, acc1[0].y, acc1[1].x, acc1[1].y);
        *(float4*)&g_accB[base + 4] = make_float4(acc1[2].x, acc1[2].y, acc1[3].x, acc1[3].y);
    }
}

// ---------------- K5: combined output GEMM [128][512] @ [512][4096], N-tile 32, grid 128 ----------------
#define K5PX 36
#define K5PW 132
__global__ void __launch_bounds__(256) k5_out() {
    __shared__ __align__(16) float xs[32*K5PX];
    __shared__ __align__(16) float sW[32*K5PW];
    const int tid = threadIdx.x;
    const int nb = blockIdx.x * 32;
    const int rg = tid >> 4, cg = tid & 15;
    const int rbase = rg * 8;
    const int lv = tid >> 3, lk = (tid & 7) * 4;

    unsigned long long acc2[8];
#pragma unroll
    for (int i = 0; i < 8; i++) acc2[i] = 0ull;

    for (int kc = 0; kc < 512; kc += 32) {
        __syncthreads();
        {
            const float* srcbuf = (kc < 256) ? g_accA : g_accB;
            const int ko = kc & 255;
            float4 x4 = *(const float4*)&srcbuf[(nb + lv)*256 + ko + lk];
            xs[(lk+0)*K5PX + lv] = x4.x;
            xs[(lk+1)*K5PX + lv] = x4.y;
            xs[(lk+2)*K5PX + lv] = x4.z;
            xs[(lk+3)*K5PX + lv] = x4.w;
        }
        for (int e = tid; e < 32*32; e += 256) {
            int k = e >> 5, c4 = e & 31;
            *(float4*)&sW[k*K5PW + c4*4] = *(const float4*)&g_WcombT[(kc + k)*128 + c4*4];
        }
        __syncthreads();
#pragma unroll
        for (int k = 0; k < 32; k++) {
            const float* wr = &sW[k*K5PW + rbase];
            float4 wa = *(const float4*)(wr);
            float4 wb = *(const float4*)(wr + 4);
            float w[8] = {wa.x, wa.y, wa.z, wa.w, wb.x, wb.y, wb.z, wb.w};
            unsigned long long xv = *(const unsigned long long*)&xs[k*K5PX + cg*2];
#pragma unroll
            for (int i = 0; i < 8; i++) {
                unsigned long long wp = pack2(w[i], w[i]);
                fma2(acc2[i], wp, xv);
            }
        }
    }
#pragma unroll
    for (int i = 0; i < 8; i++) {
        float2 f = u2f(acc2[i]);
        *(float2*)&g_outbuf[(rbase + i)*4096 + nb + cg*2] = f;
    }
}

// ---------------- K6: InstanceNorm per channel ----------------
__global__ void __launch_bounds__(256) k6_norm(const float* __restrict__ gamma,
                                               const float* __restrict__ beta,
                                               float* __restrict__ out) {
    const int c = blockIdx.x, tid = threadIdx.x;
    const float* row = &g_outbuf[c*4096];
    float s = 0.f, s2 = 0.f;
    for (int i = tid; i < 4096; i += 256) { float x = row[i]; s += x; s2 += x*x; }
#pragma unroll
    for (int m = 16; m > 0; m >>= 1) {
        s  += __shfl_xor_sync(FULL, s,  m);
        s2 += __shfl_xor_sync(FULL, s2, m);
    }
    __shared__ float rs[8], rq[8];
    __shared__ float smu, srstd;
    if ((tid & 31) == 0) { rs[tid >> 5] = s; rq[tid >> 5] = s2; }
    __syncthreads();
    if (tid == 0) {
        float ts = 0.f, tq = 0.f;
        for (int i = 0; i < 8; i++) { ts += rs[i]; tq += rq[i]; }
        float mu = ts * (1.f/4096.f);
        smu = mu;
        srstd = rsqrtf(tq * (1.f/4096.f) - mu*mu + 1e-5f);
    }
    __syncthreads();
    const float g = gamma[c] * srstd, b = beta[c], mu = smu;
    for (int i = tid; i < 4096; i += 256)
        out[c*4096 + i] = (row[i] - mu) * g + b;
}

// ---------------- launch ----------------
extern "C" void kernel_launch(void* const* d_in, const int* in_sizes, int n_in,
                              void* d_out, int out_size) {
    const float* qf    = (const float*)d_in[0];
    const float* v0    = (const float*)d_in[1];
    const float* v1    = (const float*)d_in[2];
    const float* v2    = (const float*)d_in[3];
    const float* v3    = (const float*)d_in[4];
    const float* Wq    = (const float*)d_in[5];
    const float* Wv0   = (const float*)d_in[6];
    const float* Wv1   = (const float*)d_in[7];
    const float* Wv2   = (const float*)d_in[8];
    const float* Wv3   = (const float*)d_in[9];
    const float* Woff  = (const float*)d_in[10];
    const float* boff  = (const float*)d_in[11];
    const float* Wwt   = (const float*)d_in[12];
    const float* bwt   = (const float*)d_in[13];
    const float* Wout  = (const float*)d_in[14];
    const float* gamma = (const float*)d_in[15];
    const float* beta  = (const float*)d_in[16];
    float* out = (float*)d_out;

    // R11 structure restored; ncu's captured launch (#4) is k13_fused this round.
    k0a_fold<<<640, 128>>>(Woff, Wwt, Wq, boff, bwt, Wout, Wv0);
    k0b_wvh<<<64, 128>>>(Wv1, Wv2, Wv3);
    k2_packv0<<<2048, 256>>>(v0);
    k13_fused<<<840, 256>>>(qf, v1, v2, v3);
    k4_sample<<<2048, 512>>>();
    k5_out<<<128, 256>>>();
    k6_norm<<<128, 256>>>(gamma, beta, out);
}

// round 14
// speedup vs baseline: 1.1935x; 1.0238x over previous
#include <cuda_runtime.h>
#include <cuda_fp16.h>
#include <math.h>

#define FULL 0xffffffffu

// ---------------- f32x2 packed-FMA helpers ----------------
__device__ __forceinline__ unsigned long long pack2(float a, float b) {
    unsigned long long r;
    asm("mov.b64 %0, {%1, %2};" : "=l"(r) : "f"(a), "f"(b));
    return r;
}
__device__ __forceinline__ float2 u2f(unsigned long long v) {
    float2 r;
    asm("mov.b64 {%0, %1}, %2;" : "=f"(r.x), "=f"(r.y) : "l"(v));
    return r;
}
__device__ __forceinline__ void fma2(unsigned long long& d, unsigned long long a, unsigned long long b) {
    asm("fma.rn.f32x2 %0, %1, %2, %0;" : "+l"(d) : "l"(a), "l"(b));
}
__device__ __forceinline__ float tanh_fast(float x) {
    float e = __expf(2.f * x);
    return (e - 1.f) / (e + 1.f);
}

// ---------------- scratch ----------------
// Value buffers carry zero-initialized guard tails so clamped (zero-weight)
// corner reads past the logical end stay finite.
__device__ __align__(16) float  g_W512[512*128];
__device__ float                g_b512[512];
__device__ __align__(16) float  g_WcombT[512*128];
__device__ __align__(16) __half g_Wvh[114688];
__device__ __align__(16) int2   g_mdA[524288];     // per point: {base, aw/65535}
__device__ __align__(16) uint4  g_mdB[524288];     // per point: 8x u16 corner products
__device__ __align__(16) __half g_v0ph[262144*32 + 140000];
__device__ __align__(16) __half g_val1[32768*256 + 272000];
__device__ __align__(16) __half g_val2[4096*256 + 70600];
__device__ __align__(16) __half g_val3[512*256 + 19200];
__device__ __align__(16) float  g_accA[4096*256];
__device__ __align__(16) float  g_accB[4096*256];
__device__ __align__(16) float  g_outbuf[128*4096];

// ---------------- K0a: fold W512 + build WcombT ----------------
__global__ void k0a_fold(const float* __restrict__ Woff, const float* __restrict__ Wwt,
                         const float* __restrict__ Wq,
                         const float* __restrict__ boff, const float* __restrict__ bwt,
                         const float* __restrict__ Wout, const float* __restrict__ Wv0) {
    const int b = blockIdx.x;
    const int t = threadIdx.x;
    if (b < 512) {
        const int j = b;
        const float* A = (j < 384) ? (Woff + j*192) : (Wwt + (j-384)*192);
        float s = 0.f;
        for (int m = 0; m < 192; m++) s += A[m] * Wq[m*128 + t];
        g_W512[j*128 + t] = s;
        if (t == 0) g_b512[j] = (j < 384) ? boff[j] : bwt[j-384];
    } else {
        const int c = b - 512;
#pragma unroll
        for (int kk = 0; kk < 4; kk++) {
            int k = t + kk*128;
            float s;
            if (k < 256) {
                int h = k >> 5, q = k & 31;
                s = 0.f;
                for (int j = 0; j < 24; j++)
                    s += Wout[c*192 + h*24 + j] * Wv0[(h*24 + j)*32 + q];
            } else {
                int k2 = k - 256;
                int h = k2 >> 5, j = k2 & 31;
                s = (j < 24) ? Wout[c*192 + h*24 + j] : 0.f;
            }
            g_WcombT[k*128 + c] = s;
        }
    }
}

// ---------------- K0b: build fp16 value weights ----------------
__global__ void k0b_wvh(const float* __restrict__ Wv1, const float* __restrict__ Wv2,
                        const float* __restrict__ Wv3) {
    int i = blockIdx.x*128 + threadIdx.x;
    for (int idx = i; idx < 114688; idx += 8192) {
        int row, k, C;
        const float* W;
        if (idx < 16384)      { row = idx >> 6;  k = idx & 63;  C = 64;  W = Wv1; }
        else if (idx < 49152) { int d = idx - 16384; row = d >> 7; k = d & 127; C = 128; W = Wv2; }
        else                  { int d = idx - 49152; row = d >> 8; k = d & 255; C = 256; W = Wv3; }
        int h = row >> 5, j = row & 31;
        float v = (j < 24) ? W[(h*24 + j)*C + k] : 0.f;
        g_Wvh[idx] = __float2half_rn(v);
    }
}

// ---------------- K2: transpose v0 -> fp16 [voxel][32] (standalone: high residency) ----------------
__global__ void __launch_bounds__(256) k2_packv0(const float* __restrict__ v0) {
    __shared__ float t[32*129];
    const int vb = blockIdx.x * 128;
    const int tid = threadIdx.x;
    for (int e = tid; e < 32*128; e += 256) {
        int c = e >> 7, v = e & 127;
        t[c*129 + v] = v0[c*262144 + vb + v];
    }
    __syncthreads();
    for (int e = tid; e < 512; e += 256) {
        int v = e >> 2, q = e & 3;
        union { uint4 u; __half2 h[4]; } o;
#pragma unroll
        for (int j = 0; j < 4; j++)
            o.h[j] = __floats2half2_rn(t[(q*8 + 2*j)*129 + v], t[(q*8 + 2*j + 1)*129 + v]);
        *reinterpret_cast<uint4*>(&g_v0ph[(vb + v)*32 + q*8]) = o.u;
    }
}

// ---------------- K13: merged k1 (blocks 0..255) + k3 HMMA half-tiles (256..1423) ----------------
#define K1PX 20
#define K1PW 516
__global__ void __launch_bounds__(256, 3) k13_fused(const float* __restrict__ qf,
                                                    const float* __restrict__ v1,
                                                    const float* __restrict__ v2,
                                                    const float* __restrict__ v3) {
    __shared__ __align__(16) char sm1[43264];
    const int tid = threadIdx.x;
    const int b = blockIdx.x;

    if (b < 256) {
        // ================= k1 role: 512x128 GEMM + epilogue =================
        float* xs   = (float*)sm1;            // [128][20]
        float* sW   = (float*)(sm1 + 10240);  // [16][516]
        float* sbuf = (float*)sm1;            // reuse: [512][20]

        const int nb = b * 16;
        const int rg = tid >> 2, cg = tid & 3;
        const int rbase = rg * 8, vbase = cg * 4;

        for (int e = tid; e < 128*16; e += 256) {
            int k = e >> 4, v = e & 15;
            xs[k*K1PX + v] = qf[k*4096 + nb + v];
        }
        unsigned long long acc2[8][2];
#pragma unroll
        for (int i = 0; i < 8; i++) {
            float bv = g_b512[rbase + i];
            acc2[i][0] = pack2(bv, bv);
            acc2[i][1] = acc2[i][0];
        }

        for (int kc = 0; kc < 128; kc += 16) {
            __syncthreads();
            for (int e = tid; e < 512*4; e += 256) {
                int r = e >> 2, k4 = e & 3;
                float4 w4 = *(const float4*)&g_W512[r*128 + kc + k4*4];
                sW[(k4*4+0)*K1PW + r] = w4.x;
                sW[(k4*4+1)*K1PW + r] = w4.y;
                sW[(k4*4+2)*K1PW + r] = w4.z;
                sW[(k4*4+3)*K1PW + r] = w4.w;
            }
            __syncthreads();
#pragma unroll
            for (int k = 0; k < 16; k++) {
                const float* wr = &sW[k*K1PW + rbase];
                float4 wa = *(const float4*)(wr);
                float4 wb = *(const float4*)(wr + 4);
                float w[8] = {wa.x,wa.y,wa.z,wa.w, wb.x,wb.y,wb.z,wb.w};
                ulonglong2 xv = *(const ulonglong2*)&xs[(kc + k)*K1PX + vbase];
#pragma unroll
                for (int i = 0; i < 8; i++) {
                    unsigned long long wp = pack2(w[i], w[i]);
                    fma2(acc2[i][0], wp, xv.x);
                    fma2(acc2[i][1], wp, xv.y);
                }
            }
        }
        __syncthreads();
#pragma unroll
        for (int i = 0; i < 8; i++) {
            float2 lo = u2f(acc2[i][0]), hi = u2f(acc2[i][1]);
            *(float4*)&sbuf[(rbase + i)*K1PX + vbase] = make_float4(lo.x, lo.y, hi.x, hi.y);
        }
        __syncthreads();

        // epilogue: unit u = (h,v); each thread handles 2 scales (8 points)
        const int u = tid >> 1;
        const int h = u >> 4, v = u & 15;
        const int n = nb + v;
        const int wq = n & 15, hq = (n >> 4) & 15, dq = n >> 8;
        const float bgx = -1.f + (float)wq * (2.f/15.f);
        const float bgy = -1.f + (float)hq * (2.f/15.f);
        const float bgz = -1.f + (float)dq * (2.f/15.f);
        float e[16];
        float m = -1e30f;
#pragma unroll
        for (int j = 0; j < 16; j++) {
            e[j] = sbuf[(384 + h*16 + j)*K1PX + v];
            m = fmaxf(m, e[j]);
        }
        float sum = 0.f;
#pragma unroll
        for (int j = 0; j < 16; j++) { e[j] = __expf(e[j] - m); sum += e[j]; }
        const float inv = 1.f / sum;
        const int sb = (tid & 1) * 2;
#pragma unroll
        for (int si = 0; si < 2; si++) {
            const int s = sb + si;
            const int S = 64 >> s;
            const float fS = (float)S;
            const int stride = (s == 0) ? 32 : 256;
            const int hofs = (s == 0) ? 0 : h*32;
#pragma unroll
            for (int p = 0; p < 4; p++) {
                const int rb = ((h*4 + s)*4 + p) * 3;
                float gx = bgx + tanh_fast(sbuf[(rb+0)*K1PX + v]) * 0.35f;
                float gy = bgy + tanh_fast(sbuf[(rb+1)*K1PX + v]) * 0.35f;
                float gz = bgz + tanh_fast(sbuf[(rb+2)*K1PX + v]) * 0.35f;
                float ix = fminf(fmaxf(((gx + 1.f)*fS - 1.f)*0.5f, 0.f), fS - 1.f);
                float iy = fminf(fmaxf(((gy + 1.f)*fS - 1.f)*0.5f, 0.f), fS - 1.f);
                float iz = fminf(fmaxf(((gz + 1.f)*fS - 1.f)*0.5f, 0.f), fS - 1.f);
                float x0f = floorf(ix), y0f = floorf(iy), z0f = floorf(iz);
                float wx = ix - x0f, wy = iy - y0f, wz = iz - z0f;
                int x0 = (int)x0f, y0 = (int)y0f, z0 = (int)z0f;
                int base = ((z0*S + y0)*S + x0)*stride + hofs;
                float aw = e[s*4 + p] * inv;
                float wx1 = 1.f - wx, wy1 = 1.f - wy, wz1 = 1.f - wz;
                float p00 = wz1*wy1, p01 = wz1*wy, p10 = wz*wy1, p11 = wz*wy;
                unsigned u0 = (unsigned)(p00*wx1*65535.f + 0.5f);
                unsigned u1 = (unsigned)(p00*wx *65535.f + 0.5f);
                unsigned u2 = (unsigned)(p01*wx1*65535.f + 0.5f);
                unsigned u3 = (unsigned)(p01*wx *65535.f + 0.5f);
                unsigned u4 = (unsigned)(p10*wx1*65535.f + 0.5f);
                unsigned u5 = (unsigned)(p10*wx *65535.f + 0.5f);
                unsigned u6 = (unsigned)(p11*wx1*65535.f + 0.5f);
                unsigned u7 = (unsigned)(p11*wx *65535.f + 0.5f);
                uint4 B = make_uint4((u1<<16)|u0, (u3<<16)|u2, (u5<<16)|u4, (u7<<16)|u6);
                int2 A = make_int2(base, __float_as_int(aw * (1.f/65535.f)));
                int idx = (h*16 + s*4 + p)*4096 + n;
                g_mdA[idx] = A;
                g_mdB[idx] = B;
            }
        }
        return;
    }

    // ================= k3 role: HMMA projections, half-tile per block =================
    // block handles 128 of the 256 output slots for one 64-voxel tile
    const int b2 = b - 256;
    const int half = b2 & 1, ts = b2 >> 1;
    const float* vsrc; const __half* Wg; __half* outv;
    int C, Nv, nb;
    if (ts < 512)      { vsrc = v1; Wg = g_Wvh;         outv = g_val1; C = 64;  Nv = 32768; nb = ts*64; }
    else if (ts < 576) { vsrc = v2; Wg = g_Wvh + 16384; outv = g_val2; C = 128; Nv = 4096;  nb = (ts-512)*64; }
    else               { vsrc = v3; Wg = g_Wvh + 49152; outv = g_val3; C = 256; Nv = 512;   nb = (ts-576)*64; }

    __half* Xt = (__half*)sm1;     // [64][18]
    __half* Ds = (__half*)sm1;     // reuse: [64][136]

    const int warp = tid >> 5, lane = tid & 31;
    const int grp = lane >> 2, tg = lane & 3;
    const int wbase = warp * 16;                 // slot-local base within the half
    const int rowbase = half*128 + wbase;        // global slot row

    float acc[8][4];
#pragma unroll
    for (int nt = 0; nt < 8; nt++)
#pragma unroll
        for (int i = 0; i < 4; i++) acc[nt][i] = 0.f;

    const int xk = tid >> 4, xv = (tid & 15) * 4;

    for (int kc = 0; kc < C; kc += 16) {
        float4 x4 = *(const float4*)&vsrc[(size_t)(kc + xk)*Nv + nb + xv];
        Xt[(xv+0)*18 + xk] = __float2half_rn(x4.x);
        Xt[(xv+1)*18 + xk] = __float2half_rn(x4.y);
        Xt[(xv+2)*18 + xk] = __float2half_rn(x4.z);
        Xt[(xv+3)*18 + xk] = __float2half_rn(x4.w);
        __syncthreads();

        const __half* Ar = Wg + (size_t)(rowbase + grp)*C + kc;
        unsigned af0 = *(const unsigned*)(Ar + 2*tg);
        unsigned af1 = *(const unsigned*)(Ar + 8*C + 2*tg);
        unsigned af2 = *(const unsigned*)(Ar + 2*tg + 8);
        unsigned af3 = *(const unsigned*)(Ar + 8*C + 2*tg + 8);
#pragma unroll
        for (int nt = 0; nt < 8; nt++) {
            const __half* Br = Xt + (nt*8 + grp)*18 + 2*tg;
            unsigned b0 = *(const unsigned*)Br;
            unsigned b1 = *(const unsigned*)(Br + 8);
            asm volatile(
                "mma.sync.aligned.m16n8k16.row.col.f32.f16.f16.f32 "
                "{%0,%1,%2,%3}, {%4,%5,%6,%7}, {%8,%9}, {%0,%1,%2,%3};"
                : "+f"(acc[nt][0]), "+f"(acc[nt][1]),
                  "+f"(acc[nt][2]), "+f"(acc[nt][3])
                : "r"(af0), "r"(af1), "r"(af2), "r"(af3),
                  "r"(b0), "r"(b1));
        }
        __syncthreads();
    }

    // epilogue: D[slot][vox] -> Ds[vox][slot_local] fp16
    {
        const int sl = wbase + grp;
#pragma unroll
        for (int nt = 0; nt < 8; nt++) {
            const int vv = nt*8 + 2*tg;
            Ds[vv*136 + sl]         = __float2half_rn(acc[nt][0]);
            Ds[(vv+1)*136 + sl]     = __float2half_rn(acc[nt][1]);
            Ds[vv*136 + sl + 8]     = __float2half_rn(acc[nt][2]);
            Ds[(vv+1)*136 + sl + 8] = __float2half_rn(acc[nt][3]);
        }
    }
    __syncthreads();
    for (int i = tid; i < 1024; i += 256) {
        int v = i >> 4, j = i & 15;
        *reinterpret_cast<uint4*>(&outv[(size_t)(nb + v)*256 + half*128 + j*8]) =
            *reinterpret_cast<const uint4*>(&Ds[v*136 + j*8]);
    }
}

// ---------------- K4: gather, guard-based (no border decode) ----------------
__global__ void __launch_bounds__(512, 3) k4_sample() {
    const int tid = threadIdx.x;
    const int warp = tid >> 5, lane = tid & 31;
    const int gw = blockIdx.x*16 + warp;
    const int h = gw >> 12, n = gw & 4095;
    const int corner = lane >> 2, q8 = (lane & 3) * 8;
    const int cx = corner & 1, cy = (corner >> 1) & 1, cz = corner >> 2;

    float2 acc0[4], acc1[4];
#pragma unroll
    for (int j = 0; j < 4; j++) { acc0[j] = make_float2(0.f,0.f); acc1[j] = make_float2(0.f,0.f); }

    const int ptb = h*16*4096 + n;
    const unsigned short* mdw = reinterpret_cast<const unsigned short*>(g_mdB);

    // scale 0: stride 32, S=64
    {
        const int cq = q8 + (cx ? 32 : 0) + (cy ? 64*32 : 0) + (cz ? 64*64*32 : 0);
#pragma unroll
        for (int p = 0; p < 4; p++) {
            int idx = ptb + p*4096;
            int2 A = g_mdA[idx];
            float w = (float)mdw[idx*8 + corner] * __int_as_float(A.y);
            union { uint4 u; __half2 hh[4]; } d;
            d.u = *reinterpret_cast<const uint4*>(g_v0ph + A.x + cq);
#pragma unroll
            for (int j = 0; j < 4; j++) {
                float2 f = __half22float2(d.hh[j]);
                acc0[j].x += w*f.x; acc0[j].y += w*f.y;
            }
        }
    }
    // scales 1..3: stride 256
#pragma unroll
    for (int s = 1; s < 4; s++) {
        const __half* vptr = (s == 1) ? g_val1 : (s == 2) ? g_val2 : g_val3;
        const int S = 64 >> s;
        const int cq = q8 + (cx ? 256 : 0) + (cy ? S*256 : 0) + (cz ? S*S*256 : 0);
#pragma unroll
        for (int p = 0; p < 4; p++) {
            int idx = ptb + (s*4 + p)*4096;
            int2 A = g_mdA[idx];
            float w = (float)mdw[idx*8 + corner] * __int_as_float(A.y);
            union { uint4 u; __half2 hh[4]; } d;
            d.u = *reinterpret_cast<const uint4*>(vptr + A.x + cq);
#pragma unroll
            for (int j = 0; j < 4; j++) {
                float2 f = __half22float2(d.hh[j]);
                acc1[j].x += w*f.x; acc1[j].y += w*f.y;
            }
        }
    }
#pragma unroll
    for (int m = 4; m <= 16; m <<= 1) {
#pragma unroll
        for (int j = 0; j < 4; j++) {
            acc0[j].x += __shfl_xor_sync(FULL, acc0[j].x, m);
            acc0[j].y += __shfl_xor_sync(FULL, acc0[j].y, m);
            acc1[j].x += __shfl_xor_sync(FULL, acc1[j].x, m);
            acc1[j].y += __shfl_xor_sync(FULL, acc1[j].y, m);
        }
    }
    if (lane < 4) {
        const int base = n*256 + h*32 + q8;
        *(float4*)&g_accA[base]     = make_float4(acc0[0].x, acc0[0].y, acc0[1].x, acc0[1].y);
        *(float4*)&g_accA[base + 4] = make_float4(acc0[2].x, acc0[2].y, acc0[3].x, acc0[3].y);
        *(float4*)&g_accB[base]     = make_float4(acc1[0].x, acc1[0].y, acc1[1].x, acc1[1].y);
        *(float4*)&g_accB[base + 4] = make_float4(acc1[2].x, acc1[2].y, acc1[3].x, acc1[3].y);
    }
}

// ---------------- K5: combined output GEMM [128][512] @ [512][4096], N-tile 32, grid 128 ----------------
#define K5PX 36
#define K5PW 132
__global__ void __launch_bounds__(256) k5_out() {
    __shared__ __align__(16) float xs[32*K5PX];
    __shared__ __align__(16) float sW[32*K5PW];
    const int tid = threadIdx.x;
    const int nb = blockIdx.x * 32;
    const int rg = tid >> 4, cg = tid & 15;
    const int rbase = rg * 8;
    const int lv = tid >> 3, lk = (tid & 7) * 4;

    unsigned long long acc2[8];
#pragma unroll
    for (int i = 0; i < 8; i++) acc2[i] = 0ull;

    for (int kc = 0; kc < 512; kc += 32) {
        __syncthreads();
        {
            const float* srcbuf = (kc < 256) ? g_accA : g_accB;
            const int ko = kc & 255;
            float4 x4 = *(const float4*)&srcbuf[(nb + lv)*256 + ko + lk];
            xs[(lk+0)*K5PX + lv] = x4.x;
            xs[(lk+1)*K5PX + lv] = x4.y;
            xs[(lk+2)*K5PX + lv] = x4.z;
            xs[(lk+3)*K5PX + lv] = x4.w;
        }
        for (int e = tid; e < 32*32; e += 256) {
            int k = e >> 5, c4 = e & 31;
            *(float4*)&sW[k*K5PW + c4*4] = *(const float4*)&g_WcombT[(kc + k)*128 + c4*4];
        }
        __syncthreads();
#pragma unroll
        for (int k = 0; k < 32; k++) {
            const float* wr = &sW[k*K5PW + rbase];
            float4 wa = *(const float4*)(wr);
            float4 wb = *(const float4*)(wr + 4);
            float w[8] = {wa.x, wa.y, wa.z, wa.w, wb.x, wb.y, wb.z, wb.w};
            unsigned long long xv = *(const unsigned long long*)&xs[k*K5PX + cg*2];
#pragma unroll
            for (int i = 0; i < 8; i++) {
                unsigned long long wp = pack2(w[i], w[i]);
                fma2(acc2[i], wp, xv);
            }
        }
    }
#pragma unroll
    for (int i = 0; i < 8; i++) {
        float2 f = u2f(acc2[i]);
        *(float2*)&g_outbuf[(rbase + i)*4096 + nb + cg*2] = f;
    }
}

// ---------------- K6: InstanceNorm per channel ----------------
__global__ void __launch_bounds__(256) k6_norm(const float* __restrict__ gamma,
                                               const float* __restrict__ beta,
                                               float* __restrict__ out) {
    const int c = blockIdx.x, tid = threadIdx.x;
    const float* row = &g_outbuf[c*4096];
    float s = 0.f, s2 = 0.f;
    for (int i = tid; i < 4096; i += 256) { float x = row[i]; s += x; s2 += x*x; }
#pragma unroll
    for (int m = 16; m > 0; m >>= 1) {
        s  += __shfl_xor_sync(FULL, s,  m);
        s2 += __shfl_xor_sync(FULL, s2, m);
    }
    __shared__ float rs[8], rq[8];
    __shared__ float smu, srstd;
    if ((tid & 31) == 0) { rs[tid >> 5] = s; rq[tid >> 5] = s2; }
    __syncthreads();
    if (tid == 0) {
        float ts = 0.f, tq = 0.f;
        for (int i = 0; i < 8; i++) { ts += rs[i]; tq += rq[i]; }
        float mu = ts * (1.f/4096.f);
        smu = mu;
        srstd = rsqrtf(tq * (1.f/4096.f) - mu*mu + 1e-5f);
    }
    __syncthreads();
    const float g = gamma[c] * srstd, b = beta[c], mu = smu;
    for (int i = tid; i < 4096; i += 256)
        out[c*4096 + i] = (row[i] - mu) * g + b;
}

// ---------------- launch ----------------
extern "C" void kernel_launch(void* const* d_in, const int* in_sizes, int n_in,
                              void* d_out, int out_size) {
    const float* qf    = (const float*)d_in[0];
    const float* v0    = (const float*)d_in[1];
    const float* v1    = (const float*)d_in[2];
    const float* v2    = (const float*)d_in[3];
    const float* v3    = (const float*)d_in[4];
    const float* Wq    = (const float*)d_in[5];
    const float* Wv0   = (const float*)d_in[6];
    const float* Wv1   = (const float*)d_in[7];
    const float* Wv2   = (const float*)d_in[8];
    const float* Wv3   = (const float*)d_in[9];
    const float* Woff  = (const float*)d_in[10];
    const float* boff  = (const float*)d_in[11];
    const float* Wwt   = (const float*)d_in[12];
    const float* bwt   = (const float*)d_in[13];
    const float* Wout  = (const float*)d_in[14];
    const float* gamma = (const float*)d_in[15];
    const float* beta  = (const float*)d_in[16];
    float* out = (float*)d_out;

    // ncu's captured launch (#4) is the register-fixed k13_fused.
    k0a_fold<<<640, 128>>>(Woff, Wwt, Wq, boff, bwt, Wout, Wv0);
    k0b_wvh<<<64, 128>>>(Wv1, Wv2, Wv3);
    k2_packv0<<<2048, 256>>>(v0);
    k13_fused<<<1424, 256>>>(qf, v1, v2, v3);
    k4_sample<<<2048, 512>>>();
    k5_out<<<128, 256>>>();
    k6_norm<<<128, 256>>>(gamma, beta, out);
}

// round 15
// speedup vs baseline: 1.2433x; 1.0418x over previous
#include <cuda_runtime.h>
#include <cuda_fp16.h>
#include <math.h>

#define FULL 0xffffffffu

// ---------------- f32x2 packed-FMA helpers ----------------
__device__ __forceinline__ unsigned long long pack2(float a, float b) {
    unsigned long long r;
    asm("mov.b64 %0, {%1, %2};" : "=l"(r) : "f"(a), "f"(b));
    return r;
}
__device__ __forceinline__ float2 u2f(unsigned long long v) {
    float2 r;
    asm("mov.b64 {%0, %1}, %2;" : "=f"(r.x), "=f"(r.y) : "l"(v));
    return r;
}
__device__ __forceinline__ void fma2(unsigned long long& d, unsigned long long a, unsigned long long b) {
    asm("fma.rn.f32x2 %0, %1, %2, %0;" : "+l"(d) : "l"(a), "l"(b));
}
__device__ __forceinline__ float tanh_fast(float x) {
    float e = __expf(2.f * x);
    return (e - 1.f) / (e + 1.f);
}

// ---------------- scratch ----------------
// Value buffers carry zero-initialized guard tails so clamped (zero-weight)
// corner reads past the logical end stay finite.
__device__ __align__(16) float  g_W512[512*128];
__device__ float                g_b512[512];
__device__ __align__(16) float  g_WcombT[512*128];
__device__ __align__(16) __half g_Wvh[114688];
__device__ __align__(16) int2   g_mdA[524288];     // per point: {base, aw/65535}
__device__ __align__(16) uint4  g_mdB[524288];     // per point: 8x u16 corner products
__device__ __align__(16) __half g_v0ph[262144*32 + 140000];
__device__ __align__(16) __half g_val1[32768*256 + 272000];
__device__ __align__(16) __half g_val2[4096*256 + 70600];
__device__ __align__(16) __half g_val3[512*256 + 19200];
__device__ __align__(16) float  g_accA[4096*256];
__device__ __align__(16) float  g_accB[4096*256];
__device__ __align__(16) float  g_outbuf[128*4096];

// ---------------- K0a: fold W512 + build WcombT ----------------
__global__ void k0a_fold(const float* __restrict__ Woff, const float* __restrict__ Wwt,
                         const float* __restrict__ Wq,
                         const float* __restrict__ boff, const float* __restrict__ bwt,
                         const float* __restrict__ Wout, const float* __restrict__ Wv0) {
    const int b = blockIdx.x;
    const int t = threadIdx.x;
    if (b < 512) {
        const int j = b;
        const float* A = (j < 384) ? (Woff + j*192) : (Wwt + (j-384)*192);
        float s = 0.f;
        for (int m = 0; m < 192; m++) s += A[m] * Wq[m*128 + t];
        g_W512[j*128 + t] = s;
        if (t == 0) g_b512[j] = (j < 384) ? boff[j] : bwt[j-384];
    } else {
        const int c = b - 512;
#pragma unroll
        for (int kk = 0; kk < 4; kk++) {
            int k = t + kk*128;
            float s;
            if (k < 256) {
                int h = k >> 5, q = k & 31;
                s = 0.f;
                for (int j = 0; j < 24; j++)
                    s += Wout[c*192 + h*24 + j] * Wv0[(h*24 + j)*32 + q];
            } else {
                int k2 = k - 256;
                int h = k2 >> 5, j = k2 & 31;
                s = (j < 24) ? Wout[c*192 + h*24 + j] : 0.f;
            }
            g_WcombT[k*128 + c] = s;
        }
    }
}

// ---------------- K0b: build fp16 value weights ----------------
__global__ void k0b_wvh(const float* __restrict__ Wv1, const float* __restrict__ Wv2,
                        const float* __restrict__ Wv3) {
    int i = blockIdx.x*128 + threadIdx.x;
    for (int idx = i; idx < 114688; idx += 8192) {
        int row, k, C;
        const float* W;
        if (idx < 16384)      { row = idx >> 6;  k = idx & 63;  C = 64;  W = Wv1; }
        else if (idx < 49152) { int d = idx - 16384; row = d >> 7; k = d & 127; C = 128; W = Wv2; }
        else                  { int d = idx - 49152; row = d >> 8; k = d & 255; C = 256; W = Wv3; }
        int h = row >> 5, j = row & 31;
        float v = (j < 24) ? W[(h*24 + j)*C + k] : 0.f;
        g_Wvh[idx] = __float2half_rn(v);
    }
}

// ---------------- K2: transpose v0 -> fp16 [voxel][32] (standalone: high residency) ----------------
__global__ void __launch_bounds__(256) k2_packv0(const float* __restrict__ v0) {
    __shared__ float t[32*129];
    const int vb = blockIdx.x * 128;
    const int tid = threadIdx.x;
    for (int e = tid; e < 32*128; e += 256) {
        int c = e >> 7, v = e & 127;
        t[c*129 + v] = v0[c*262144 + vb + v];
    }
    __syncthreads();
    for (int e = tid; e < 512; e += 256) {
        int v = e >> 2, q = e & 3;
        union { uint4 u; __half2 h[4]; } o;
#pragma unroll
        for (int j = 0; j < 4; j++)
            o.h[j] = __floats2half2_rn(t[(q*8 + 2*j)*129 + v], t[(q*8 + 2*j + 1)*129 + v]);
        *reinterpret_cast<uint4*>(&g_v0ph[(vb + v)*32 + q*8]) = o.u;
    }
}

// ---------------- K13: merged k1 (blocks 0..255) + k3 HMMA half-tiles (256..1423) ----------------
#define K1PX 20
#define K1PW 516
__global__ void __launch_bounds__(256, 3) k13_fused(const float* __restrict__ qf,
                                                    const float* __restrict__ v1,
                                                    const float* __restrict__ v2,
                                                    const float* __restrict__ v3) {
    __shared__ __align__(16) char sm1[43264];
    const int tid = threadIdx.x;
    const int b = blockIdx.x;

    if (b < 256) {
        // ================= k1 role: 512x128 GEMM + epilogue =================
        float* xs   = (float*)sm1;            // [128][20]
        float* sW   = (float*)(sm1 + 10240);  // [16][516]
        float* sbuf = (float*)sm1;            // reuse: [512][20]

        const int nb = b * 16;
        const int rg = tid >> 2, cg = tid & 3;
        const int rbase = rg * 8, vbase = cg * 4;

        for (int e = tid; e < 128*16; e += 256) {
            int k = e >> 4, v = e & 15;
            xs[k*K1PX + v] = qf[k*4096 + nb + v];
        }
        unsigned long long acc2[8][2];
#pragma unroll
        for (int i = 0; i < 8; i++) {
            float bv = g_b512[rbase + i];
            acc2[i][0] = pack2(bv, bv);
            acc2[i][1] = acc2[i][0];
        }

        for (int kc = 0; kc < 128; kc += 16) {
            __syncthreads();
            for (int e = tid; e < 512*4; e += 256) {
                int r = e >> 2, k4 = e & 3;
                float4 w4 = *(const float4*)&g_W512[r*128 + kc + k4*4];
                sW[(k4*4+0)*K1PW + r] = w4.x;
                sW[(k4*4+1)*K1PW + r] = w4.y;
                sW[(k4*4+2)*K1PW + r] = w4.z;
                sW[(k4*4+3)*K1PW + r] = w4.w;
            }
            __syncthreads();
#pragma unroll
            for (int k = 0; k < 16; k++) {
                const float* wr = &sW[k*K1PW + rbase];
                float4 wa = *(const float4*)(wr);
                float4 wb = *(const float4*)(wr + 4);
                float w[8] = {wa.x,wa.y,wa.z,wa.w, wb.x,wb.y,wb.z,wb.w};
                ulonglong2 xv = *(const ulonglong2*)&xs[(kc + k)*K1PX + vbase];
#pragma unroll
                for (int i = 0; i < 8; i++) {
                    unsigned long long wp = pack2(w[i], w[i]);
                    fma2(acc2[i][0], wp, xv.x);
                    fma2(acc2[i][1], wp, xv.y);
                }
            }
        }
        __syncthreads();
#pragma unroll
        for (int i = 0; i < 8; i++) {
            float2 lo = u2f(acc2[i][0]), hi = u2f(acc2[i][1]);
            *(float4*)&sbuf[(rbase + i)*K1PX + vbase] = make_float4(lo.x, lo.y, hi.x, hi.y);
        }
        __syncthreads();

        // epilogue: unit u = (h,v); each thread handles 2 scales (8 points)
        const int u = tid >> 1;
        const int h = u >> 4, v = u & 15;
        const int n = nb + v;
        const int wq = n & 15, hq = (n >> 4) & 15, dq = n >> 8;
        const float bgx = -1.f + (float)wq * (2.f/15.f);
        const float bgy = -1.f + (float)hq * (2.f/15.f);
        const float bgz = -1.f + (float)dq * (2.f/15.f);
        float e[16];
        float m = -1e30f;
#pragma unroll
        for (int j = 0; j < 16; j++) {
            e[j] = sbuf[(384 + h*16 + j)*K1PX + v];
            m = fmaxf(m, e[j]);
        }
        float sum = 0.f;
#pragma unroll
        for (int j = 0; j < 16; j++) { e[j] = __expf(e[j] - m); sum += e[j]; }
        const float inv = 1.f / sum;
        const int sb = (tid & 1) * 2;
#pragma unroll
        for (int si = 0; si < 2; si++) {
            const int s = sb + si;
            const int S = 64 >> s;
            const float fS = (float)S;
            const int stride = (s == 0) ? 32 : 256;
            const int hofs = (s == 0) ? 0 : h*32;
#pragma unroll
            for (int p = 0; p < 4; p++) {
                const int rb = ((h*4 + s)*4 + p) * 3;
                float gx = bgx + tanh_fast(sbuf[(rb+0)*K1PX + v]) * 0.35f;
                float gy = bgy + tanh_fast(sbuf[(rb+1)*K1PX + v]) * 0.35f;
                float gz = bgz + tanh_fast(sbuf[(rb+2)*K1PX + v]) * 0.35f;
                float ix = fminf(fmaxf(((gx + 1.f)*fS - 1.f)*0.5f, 0.f), fS - 1.f);
                float iy = fminf(fmaxf(((gy + 1.f)*fS - 1.f)*0.5f, 0.f), fS - 1.f);
                float iz = fminf(fmaxf(((gz + 1.f)*fS - 1.f)*0.5f, 0.f), fS - 1.f);
                float x0f = floorf(ix), y0f = floorf(iy), z0f = floorf(iz);
                float wx = ix - x0f, wy = iy - y0f, wz = iz - z0f;
                int x0 = (int)x0f, y0 = (int)y0f, z0 = (int)z0f;
                int base = ((z0*S + y0)*S + x0)*stride + hofs;
                float aw = e[s*4 + p] * inv;
                float wx1 = 1.f - wx, wy1 = 1.f - wy, wz1 = 1.f - wz;
                float p00 = wz1*wy1, p01 = wz1*wy, p10 = wz*wy1, p11 = wz*wy;
                unsigned u0 = (unsigned)(p00*wx1*65535.f + 0.5f);
                unsigned u1 = (unsigned)(p00*wx *65535.f + 0.5f);
                unsigned u2 = (unsigned)(p01*wx1*65535.f + 0.5f);
                unsigned u3 = (unsigned)(p01*wx *65535.f + 0.5f);
                unsigned u4 = (unsigned)(p10*wx1*65535.f + 0.5f);
                unsigned u5 = (unsigned)(p10*wx *65535.f + 0.5f);
                unsigned u6 = (unsigned)(p11*wx1*65535.f + 0.5f);
                unsigned u7 = (unsigned)(p11*wx *65535.f + 0.5f);
                uint4 B = make_uint4((u1<<16)|u0, (u3<<16)|u2, (u5<<16)|u4, (u7<<16)|u6);
                int2 A = make_int2(base, __float_as_int(aw * (1.f/65535.f)));
                int idx = (h*16 + s*4 + p)*4096 + n;
                g_mdA[idx] = A;
                g_mdB[idx] = B;
            }
        }
        return;
    }

    // ================= k3 role: HMMA projections, half-tile per block =================
    const int b2 = b - 256;
    const int half = b2 & 1, ts = b2 >> 1;
    const float* vsrc; const __half* Wg; __half* outv;
    int C, Nv, nb;
    if (ts < 512)      { vsrc = v1; Wg = g_Wvh;         outv = g_val1; C = 64;  Nv = 32768; nb = ts*64; }
    else if (ts < 576) { vsrc = v2; Wg = g_Wvh + 16384; outv = g_val2; C = 128; Nv = 4096;  nb = (ts-512)*64; }
    else               { vsrc = v3; Wg = g_Wvh + 49152; outv = g_val3; C = 256; Nv = 512;   nb = (ts-576)*64; }

    __half* Xt = (__half*)sm1;     // [64][18]
    __half* Ds = (__half*)sm1;     // reuse: [64][136]

    const int warp = tid >> 5, lane = tid & 31;
    const int grp = lane >> 2, tg = lane & 3;
    const int wbase = warp * 16;
    const int rowbase = half*128 + wbase;

    float acc[8][4];
#pragma unroll
    for (int nt = 0; nt < 8; nt++)
#pragma unroll
        for (int i = 0; i < 4; i++) acc[nt][i] = 0.f;

    const int xk = tid >> 4, xv = (tid & 15) * 4;

    for (int kc = 0; kc < C; kc += 16) {
        float4 x4 = *(const float4*)&vsrc[(size_t)(kc + xk)*Nv + nb + xv];
        Xt[(xv+0)*18 + xk] = __float2half_rn(x4.x);
        Xt[(xv+1)*18 + xk] = __float2half_rn(x4.y);
        Xt[(xv+2)*18 + xk] = __float2half_rn(x4.z);
        Xt[(xv+3)*18 + xk] = __float2half_rn(x4.w);
        __syncthreads();

        const __half* Ar = Wg + (size_t)(rowbase + grp)*C + kc;
        unsigned af0 = *(const unsigned*)(Ar + 2*tg);
        unsigned af1 = *(const unsigned*)(Ar + 8*C + 2*tg);
        unsigned af2 = *(const unsigned*)(Ar + 2*tg + 8);
        unsigned af3 = *(const unsigned*)(Ar + 8*C + 2*tg + 8);
#pragma unroll
        for (int nt = 0; nt < 8; nt++) {
            const __half* Br = Xt + (nt*8 + grp)*18 + 2*tg;
            unsigned b0 = *(const unsigned*)Br;
            unsigned b1 = *(const unsigned*)(Br + 8);
            asm volatile(
                "mma.sync.aligned.m16n8k16.row.col.f32.f16.f16.f32 "
                "{%0,%1,%2,%3}, {%4,%5,%6,%7}, {%8,%9}, {%0,%1,%2,%3};"
                : "+f"(acc[nt][0]), "+f"(acc[nt][1]),
                  "+f"(acc[nt][2]), "+f"(acc[nt][3])
                : "r"(af0), "r"(af1), "r"(af2), "r"(af3),
                  "r"(b0), "r"(b1));
        }
        __syncthreads();
    }

    {
        const int sl = wbase + grp;
#pragma unroll
        for (int nt = 0; nt < 8; nt++) {
            const int vv = nt*8 + 2*tg;
            Ds[vv*136 + sl]         = __float2half_rn(acc[nt][0]);
            Ds[(vv+1)*136 + sl]     = __float2half_rn(acc[nt][1]);
            Ds[vv*136 + sl + 8]     = __float2half_rn(acc[nt][2]);
            Ds[(vv+1)*136 + sl + 8] = __float2half_rn(acc[nt][3]);
        }
    }
    __syncthreads();
    for (int i = tid; i < 1024; i += 256) {
        int v = i >> 4, j = i & 15;
        *reinterpret_cast<uint4*>(&outv[(size_t)(nb + v)*256 + half*128 + j*8]) =
            *reinterpret_cast<const uint4*>(&Ds[v*136 + j*8]);
    }
}

// ---------------- K4: gather, guard-based (no border decode) ----------------
__global__ void __launch_bounds__(512, 3) k4_sample() {
    const int tid = threadIdx.x;
    const int warp = tid >> 5, lane = tid & 31;
    const int gw = blockIdx.x*16 + warp;
    const int h = gw >> 12, n = gw & 4095;
    const int corner = lane >> 2, q8 = (lane & 3) * 8;
    const int cx = corner & 1, cy = (corner >> 1) & 1, cz = corner >> 2;

    float2 acc0[4], acc1[4];
#pragma unroll
    for (int j = 0; j < 4; j++) { acc0[j] = make_float2(0.f,0.f); acc1[j] = make_float2(0.f,0.f); }

    const int ptb = h*16*4096 + n;
    const unsigned short* mdw = reinterpret_cast<const unsigned short*>(g_mdB);

    // scale 0: stride 32, S=64
    {
        const int cq = q8 + (cx ? 32 : 0) + (cy ? 64*32 : 0) + (cz ? 64*64*32 : 0);
#pragma unroll
        for (int p = 0; p < 4; p++) {
            int idx = ptb + p*4096;
            int2 A = g_mdA[idx];
            float w = (float)mdw[idx*8 + corner] * __int_as_float(A.y);
            union { uint4 u; __half2 hh[4]; } d;
            d.u = *reinterpret_cast<const uint4*>(g_v0ph + A.x + cq);
#pragma unroll
            for (int j = 0; j < 4; j++) {
                float2 f = __half22float2(d.hh[j]);
                acc0[j].x += w*f.x; acc0[j].y += w*f.y;
            }
        }
    }
    // scales 1..3: stride 256
#pragma unroll
    for (int s = 1; s < 4; s++) {
        const __half* vptr = (s == 1) ? g_val1 : (s == 2) ? g_val2 : g_val3;
        const int S = 64 >> s;
        const int cq = q8 + (cx ? 256 : 0) + (cy ? S*256 : 0) + (cz ? S*S*256 : 0);
#pragma unroll
        for (int p = 0; p < 4; p++) {
            int idx = ptb + (s*4 + p)*4096;
            int2 A = g_mdA[idx];
            float w = (float)mdw[idx*8 + corner] * __int_as_float(A.y);
            union { uint4 u; __half2 hh[4]; } d;
            d.u = *reinterpret_cast<const uint4*>(vptr + A.x + cq);
#pragma unroll
            for (int j = 0; j < 4; j++) {
                float2 f = __half22float2(d.hh[j]);
                acc1[j].x += w*f.x; acc1[j].y += w*f.y;
            }
        }
    }
#pragma unroll
    for (int m = 4; m <= 16; m <<= 1) {
#pragma unroll
        for (int j = 0; j < 4; j++) {
            acc0[j].x += __shfl_xor_sync(FULL, acc0[j].x, m);
            acc0[j].y += __shfl_xor_sync(FULL, acc0[j].y, m);
            acc1[j].x += __shfl_xor_sync(FULL, acc1[j].x, m);
            acc1[j].y += __shfl_xor_sync(FULL, acc1[j].y, m);
        }
    }
    if (lane < 4) {
        const int base = n*256 + h*32 + q8;
        *(float4*)&g_accA[base]     = make_float4(acc0[0].x, acc0[0].y, acc0[1].x, acc0[1].y);
        *(float4*)&g_accA[base + 4] = make_float4(acc0[2].x, acc0[2].y, acc0[3].x, acc0[3].y);
        *(float4*)&g_accB[base]     = make_float4(acc1[0].x, acc1[0].y, acc1[1].x, acc1[1].y);
        *(float4*)&g_accB[base + 4] = make_float4(acc1[2].x, acc1[2].y, acc1[3].x, acc1[3].y);
    }
}

// ---------------- K5: combined output GEMM [128][512] @ [512][4096], N-tile 32, grid 128 ----------------
#define K5PX 36
#define K5PW 132
__global__ void __launch_bounds__(256) k5_out() {
    __shared__ __align__(16) float xs[32*K5PX];
    __shared__ __align__(16) float sW[32*K5PW];
    const int tid = threadIdx.x;
    const int nb = blockIdx.x * 32;
    const int rg = tid >> 4, cg = tid & 15;
    const int rbase = rg * 8;
    const int lv = tid >> 3, lk = (tid & 7) * 4;

    unsigned long long acc2[8];
#pragma unroll
    for (int i = 0; i < 8; i++) acc2[i] = 0ull;

    for (int kc = 0; kc < 512; kc += 32) {
        __syncthreads();
        {
            const float* srcbuf = (kc < 256) ? g_accA : g_accB;
            const int ko = kc & 255;
            float4 x4 = *(const float4*)&srcbuf[(nb + lv)*256 + ko + lk];
            xs[(lk+0)*K5PX + lv] = x4.x;
            xs[(lk+1)*K5PX + lv] = x4.y;
            xs[(lk+2)*K5PX + lv] = x4.z;
            xs[(lk+3)*K5PX + lv] = x4.w;
        }
        for (int e = tid; e < 32*32; e += 256) {
            int k = e >> 5, c4 = e & 31;
            *(float4*)&sW[k*K5PW + c4*4] = *(const float4*)&g_WcombT[(kc + k)*128 + c4*4];
        }
        __syncthreads();
#pragma unroll
        for (int k = 0; k < 32; k++) {
            const float* wr = &sW[k*K5PW + rbase];
            float4 wa = *(const float4*)(wr);
            float4 wb = *(const float4*)(wr + 4);
            float w[8] = {wa.x, wa.y, wa.z, wa.w, wb.x, wb.y, wb.z, wb.w};
            unsigned long long xv = *(const unsigned long long*)&xs[k*K5PX + cg*2];
#pragma unroll
            for (int i = 0; i < 8; i++) {
                unsigned long long wp = pack2(w[i], w[i]);
                fma2(acc2[i], wp, xv);
            }
        }
    }
#pragma unroll
    for (int i = 0; i < 8; i++) {
        float2 f = u2f(acc2[i]);
        *(float2*)&g_outbuf[(rbase + i)*4096 + nb + cg*2] = f;
    }
}

// ---------------- K6: InstanceNorm per channel ----------------
__global__ void __launch_bounds__(256) k6_norm(const float* __restrict__ gamma,
                                               const float* __restrict__ beta,
                                               float* __restrict__ out) {
    const int c = blockIdx.x, tid = threadIdx.x;
    const float* row = &g_outbuf[c*4096];
    float s = 0.f, s2 = 0.f;
    for (int i = tid; i < 4096; i += 256) { float x = row[i]; s += x; s2 += x*x; }
#pragma unroll
    for (int m = 16; m > 0; m >>= 1) {
        s  += __shfl_xor_sync(FULL, s,  m);
        s2 += __shfl_xor_sync(FULL, s2, m);
    }
    __shared__ float rs[8], rq[8];
    __shared__ float smu, srstd;
    if ((tid & 31) == 0) { rs[tid >> 5] = s; rq[tid >> 5] = s2; }
    __syncthreads();
    if (tid == 0) {
        float ts = 0.f, tq = 0.f;
        for (int i = 0; i < 8; i++) { ts += rs[i]; tq += rq[i]; }
        float mu = ts * (1.f/4096.f);
        smu = mu;
        srstd = rsqrtf(tq * (1.f/4096.f) - mu*mu + 1e-5f);
    }
    __syncthreads();
    const float g = gamma[c] * srstd, b = beta[c], mu = smu;
    for (int i = tid; i < 4096; i += 256)
        out[c*4096 + i] = (row[i] - mu) * g + b;
}

// ---------------- launch ----------------
extern "C" void kernel_launch(void* const* d_in, const int* in_sizes, int n_in,
                              void* d_out, int out_size) {
    const float* qf    = (const float*)d_in[0];
    const float* v0    = (const float*)d_in[1];
    const float* v1    = (const float*)d_in[2];
    const float* v2    = (const float*)d_in[3];
    const float* v3    = (const float*)d_in[4];
    const float* Wq    = (const float*)d_in[5];
    const float* Wv0   = (const float*)d_in[6];
    const float* Wv1   = (const float*)d_in[7];
    const float* Wv2   = (const float*)d_in[8];
    const float* Wv3   = (const float*)d_in[9];
    const float* Woff  = (const float*)d_in[10];
    const float* boff  = (const float*)d_in[11];
    const float* Wwt   = (const float*)d_in[12];
    const float* bwt   = (const float*)d_in[13];
    const float* Wout  = (const float*)d_in[14];
    const float* gamma = (const float*)d_in[15];
    const float* beta  = (const float*)d_in[16];
    float* out = (float*)d_out;

    // Lazily-created side stream + events (first call is the uncaptured
    // correctness run; subsequent graph-capture call reuses them, and the
    // event record/wait pattern becomes graph fork/join edges).
    static cudaStream_t s_side = nullptr;
    static cudaEvent_t  ev_fork = nullptr, ev_k2 = nullptr;
    static bool s_ok = false;
    if (!s_side) {
        bool ok = (cudaStreamCreateWithFlags(&s_side, cudaStreamNonBlocking) == cudaSuccess);
        ok = ok && (cudaEventCreateWithFlags(&ev_fork, cudaEventDisableTiming) == cudaSuccess);
        ok = ok && (cudaEventCreateWithFlags(&ev_k2,  cudaEventDisableTiming) == cudaSuccess);
        s_ok = ok;
    }

    if (s_ok) {
        // fork: k2 (DRAM-streaming, independent) runs concurrently with k0a/k0b/k13
        cudaEventRecord(ev_fork, 0);
        cudaStreamWaitEvent(s_side, ev_fork, 0);
        k2_packv0<<<2048, 256, 0, s_side>>>(v0);
        cudaEventRecord(ev_k2, s_side);

        k0a_fold<<<640, 128>>>(Woff, Wwt, Wq, boff, bwt, Wout, Wv0);
        k0b_wvh<<<64, 128>>>(Wv1, Wv2, Wv3);
        k13_fused<<<1424, 256>>>(qf, v1, v2, v3);

        // join before k4 (k4 reads g_v0ph)
        cudaStreamWaitEvent(0, ev_k2, 0);
        k4_sample<<<2048, 512>>>();
        k5_out<<<128, 256>>>();
        k6_norm<<<128, 256>>>(gamma, beta, out);
    } else {
        k0a_fold<<<640, 128>>>(Woff, Wwt, Wq, boff, bwt, Wout, Wv0);
        k0b_wvh<<<64, 128>>>(Wv1, Wv2, Wv3);
        k2_packv0<<<2048, 256>>>(v0);
        k13_fused<<<1424, 256>>>(qf, v1, v2, v3);
        k4_sample<<<2048, 512>>>();
        k5_out<<<128, 256>>>();
        k6_norm<<<128, 256>>>(gamma, beta, out);
    }
}

// round 16
// speedup vs baseline: 1.2529x; 1.0077x over previous
#include <cuda_runtime.h>
#include <cuda_fp16.h>
#include <math.h>

#define FULL 0xffffffffu

// ---------------- f32x2 packed-FMA helpers ----------------
__device__ __forceinline__ unsigned long long pack2(float a, float b) {
    unsigned long long r;
    asm("mov.b64 %0, {%1, %2};" : "=l"(r) : "f"(a), "f"(b));
    return r;
}
__device__ __forceinline__ float2 u2f(unsigned long long v) {
    float2 r;
    asm("mov.b64 {%0, %1}, %2;" : "=f"(r.x), "=f"(r.y) : "l"(v));
    return r;
}
__device__ __forceinline__ void fma2(unsigned long long& d, unsigned long long a, unsigned long long b) {
    asm("fma.rn.f32x2 %0, %1, %2, %0;" : "+l"(d) : "l"(a), "l"(b));
}
__device__ __forceinline__ float tanh_fast(float x) {
    float e = __expf(2.f * x);
    return (e - 1.f) / (e + 1.f);
}

// ---------------- scratch ----------------
// Value buffers carry zero-initialized guard tails so clamped (zero-weight)
// corner reads past the logical end stay finite.
__device__ __align__(16) float  g_W512[512*128];
__device__ float                g_b512[512];
__device__ __align__(16) float  g_WcombT[512*128];
__device__ __align__(16) __half g_Wvh[114688];
__device__ __align__(16) int2   g_mdA[524288];     // per point: {base, aw/65535}
__device__ __align__(16) uint4  g_mdB[524288];     // per point: 8x u16 corner products
__device__ __align__(16) __half g_v0ph[262144*32 + 140000];
__device__ __align__(16) __half g_val1[32768*256 + 272000];
__device__ __align__(16) __half g_val2[4096*256 + 70600];
__device__ __align__(16) __half g_val3[512*256 + 19200];
__device__ __align__(16) float  g_accA[4096*256];
__device__ __align__(16) float  g_accB[4096*256];
__device__ __align__(16) float  g_outbuf[128*4096];

// ---------------- K0a: fold W512 + build WcombT ----------------
__global__ void k0a_fold(const float* __restrict__ Woff, const float* __restrict__ Wwt,
                         const float* __restrict__ Wq,
                         const float* __restrict__ boff, const float* __restrict__ bwt,
                         const float* __restrict__ Wout, const float* __restrict__ Wv0) {
    const int b = blockIdx.x;
    const int t = threadIdx.x;
    if (b < 512) {
        const int j = b;
        const float* A = (j < 384) ? (Woff + j*192) : (Wwt + (j-384)*192);
        float s = 0.f;
        for (int m = 0; m < 192; m++) s += A[m] * Wq[m*128 + t];
        g_W512[j*128 + t] = s;
        if (t == 0) g_b512[j] = (j < 384) ? boff[j] : bwt[j-384];
    } else {
        const int c = b - 512;
#pragma unroll
        for (int kk = 0; kk < 4; kk++) {
            int k = t + kk*128;
            float s;
            if (k < 256) {
                int h = k >> 5, q = k & 31;
                s = 0.f;
                for (int j = 0; j < 24; j++)
                    s += Wout[c*192 + h*24 + j] * Wv0[(h*24 + j)*32 + q];
            } else {
                int k2 = k - 256;
                int h = k2 >> 5, j = k2 & 31;
                s = (j < 24) ? Wout[c*192 + h*24 + j] : 0.f;
            }
            g_WcombT[k*128 + c] = s;
        }
    }
}

// ---------------- K0b: build fp16 value weights ----------------
__global__ void k0b_wvh(const float* __restrict__ Wv1, const float* __restrict__ Wv2,
                        const float* __restrict__ Wv3) {
    int i = blockIdx.x*128 + threadIdx.x;
    for (int idx = i; idx < 114688; idx += 8192) {
        int row, k, C;
        const float* W;
        if (idx < 16384)      { row = idx >> 6;  k = idx & 63;  C = 64;  W = Wv1; }
        else if (idx < 49152) { int d = idx - 16384; row = d >> 7; k = d & 127; C = 128; W = Wv2; }
        else                  { int d = idx - 49152; row = d >> 8; k = d & 255; C = 256; W = Wv3; }
        int h = row >> 5, j = row & 31;
        float v = (j < 24) ? W[(h*24 + j)*C + k] : 0.f;
        g_Wvh[idx] = __float2half_rn(v);
    }
}

// ---------------- K2: transpose v0 -> fp16 [voxel][32] ----------------
__global__ void __launch_bounds__(256) k2_packv0(const float* __restrict__ v0) {
    __shared__ float t[32*129];
    const int vb = blockIdx.x * 128;
    const int tid = threadIdx.x;
    for (int e = tid; e < 32*128; e += 256) {
        int c = e >> 7, v = e & 127;
        t[c*129 + v] = v0[c*262144 + vb + v];
    }
    __syncthreads();
    for (int e = tid; e < 512; e += 256) {
        int v = e >> 2, q = e & 3;
        union { uint4 u; __half2 h[4]; } o;
#pragma unroll
        for (int j = 0; j < 4; j++)
            o.h[j] = __floats2half2_rn(t[(q*8 + 2*j)*129 + v], t[(q*8 + 2*j + 1)*129 + v]);
        *reinterpret_cast<uint4*>(&g_v0ph[(vb + v)*32 + q*8]) = o.u;
    }
}

// ---------------- K1: 512x128 GEMM (f32x2) + epilogue + md emit (standalone) ----------------
#define K1PX 20
#define K1PW 516
__global__ void __launch_bounds__(256) k1_offaw(const float* __restrict__ qf) {
    __shared__ __align__(16) char sm1[43264];
    float* xs   = (float*)sm1;            // [128][20]
    float* sW   = (float*)(sm1 + 10240);  // [16][516]
    float* sbuf = (float*)sm1;            // reuse: [512][20]

    const int nb = blockIdx.x * 16;
    const int tid = threadIdx.x;
    const int rg = tid >> 2, cg = tid & 3;
    const int rbase = rg * 8, vbase = cg * 4;

    for (int e = tid; e < 128*16; e += 256) {
        int k = e >> 4, v = e & 15;
        xs[k*K1PX + v] = qf[k*4096 + nb + v];
    }
    unsigned long long acc2[8][2];
#pragma unroll
    for (int i = 0; i < 8; i++) {
        float bv = g_b512[rbase + i];
        acc2[i][0] = pack2(bv, bv);
        acc2[i][1] = acc2[i][0];
    }

    for (int kc = 0; kc < 128; kc += 16) {
        __syncthreads();
        for (int e = tid; e < 512*4; e += 256) {
            int r = e >> 2, k4 = e & 3;
            float4 w4 = *(const float4*)&g_W512[r*128 + kc + k4*4];
            sW[(k4*4+0)*K1PW + r] = w4.x;
            sW[(k4*4+1)*K1PW + r] = w4.y;
            sW[(k4*4+2)*K1PW + r] = w4.z;
            sW[(k4*4+3)*K1PW + r] = w4.w;
        }
        __syncthreads();
#pragma unroll
        for (int k = 0; k < 16; k++) {
            const float* wr = &sW[k*K1PW + rbase];
            float4 wa = *(const float4*)(wr);
            float4 wb = *(const float4*)(wr + 4);
            float w[8] = {wa.x,wa.y,wa.z,wa.w, wb.x,wb.y,wb.z,wb.w};
            ulonglong2 xv = *(const ulonglong2*)&xs[(kc + k)*K1PX + vbase];
#pragma unroll
            for (int i = 0; i < 8; i++) {
                unsigned long long wp = pack2(w[i], w[i]);
                fma2(acc2[i][0], wp, xv.x);
                fma2(acc2[i][1], wp, xv.y);
            }
        }
    }
    __syncthreads();
#pragma unroll
    for (int i = 0; i < 8; i++) {
        float2 lo = u2f(acc2[i][0]), hi = u2f(acc2[i][1]);
        *(float4*)&sbuf[(rbase + i)*K1PX + vbase] = make_float4(lo.x, lo.y, hi.x, hi.y);
    }
    __syncthreads();

    // epilogue: unit u = (h,v); each thread handles 2 scales (8 points)
    const int u = tid >> 1;
    const int h = u >> 4, v = u & 15;
    const int n = nb + v;
    const int wq = n & 15, hq = (n >> 4) & 15, dq = n >> 8;
    const float bgx = -1.f + (float)wq * (2.f/15.f);
    const float bgy = -1.f + (float)hq * (2.f/15.f);
    const float bgz = -1.f + (float)dq * (2.f/15.f);
    float e[16];
    float m = -1e30f;
#pragma unroll
    for (int j = 0; j < 16; j++) {
        e[j] = sbuf[(384 + h*16 + j)*K1PX + v];
        m = fmaxf(m, e[j]);
    }
    float sum = 0.f;
#pragma unroll
    for (int j = 0; j < 16; j++) { e[j] = __expf(e[j] - m); sum += e[j]; }
    const float inv = 1.f / sum;
    const int sb = (tid & 1) * 2;
#pragma unroll
    for (int si = 0; si < 2; si++) {
        const int s = sb + si;
        const int S = 64 >> s;
        const float fS = (float)S;
        const int stride = (s == 0) ? 32 : 256;
        const int hofs = (s == 0) ? 0 : h*32;
#pragma unroll
        for (int p = 0; p < 4; p++) {
            const int rb = ((h*4 + s)*4 + p) * 3;
            float gx = bgx + tanh_fast(sbuf[(rb+0)*K1PX + v]) * 0.35f;
            float gy = bgy + tanh_fast(sbuf[(rb+1)*K1PX + v]) * 0.35f;
            float gz = bgz + tanh_fast(sbuf[(rb+2)*K1PX + v]) * 0.35f;
            float ix = fminf(fmaxf(((gx + 1.f)*fS - 1.f)*0.5f, 0.f), fS - 1.f);
            float iy = fminf(fmaxf(((gy + 1.f)*fS - 1.f)*0.5f, 0.f), fS - 1.f);
            float iz = fminf(fmaxf(((gz + 1.f)*fS - 1.f)*0.5f, 0.f), fS - 1.f);
            float x0f = floorf(ix), y0f = floorf(iy), z0f = floorf(iz);
            float wx = ix - x0f, wy = iy - y0f, wz = iz - z0f;
            int x0 = (int)x0f, y0 = (int)y0f, z0 = (int)z0f;
            int base = ((z0*S + y0)*S + x0)*stride + hofs;
            float aw = e[s*4 + p] * inv;
            float wx1 = 1.f - wx, wy1 = 1.f - wy, wz1 = 1.f - wz;
            float p00 = wz1*wy1, p01 = wz1*wy, p10 = wz*wy1, p11 = wz*wy;
            unsigned u0 = (unsigned)(p00*wx1*65535.f + 0.5f);
            unsigned u1 = (unsigned)(p00*wx *65535.f + 0.5f);
            unsigned u2 = (unsigned)(p01*wx1*65535.f + 0.5f);
            unsigned u3 = (unsigned)(p01*wx *65535.f + 0.5f);
            unsigned u4 = (unsigned)(p10*wx1*65535.f + 0.5f);
            unsigned u5 = (unsigned)(p10*wx *65535.f + 0.5f);
            unsigned u6 = (unsigned)(p11*wx1*65535.f + 0.5f);
            unsigned u7 = (unsigned)(p11*wx *65535.f + 0.5f);
            uint4 B = make_uint4((u1<<16)|u0, (u3<<16)|u2, (u5<<16)|u4, (u7<<16)|u6);
            int2 A = make_int2(base, __float_as_int(aw * (1.f/65535.f)));
            int idx = (h*16 + s*4 + p)*4096 + n;
            g_mdA[idx] = A;
            g_mdB[idx] = B;
        }
    }
}

// ---------------- K3: HMMA projections, half-tile per block (standalone) ----------------
__global__ void __launch_bounds__(256) k3_proj(const float* __restrict__ v1,
                                               const float* __restrict__ v2,
                                               const float* __restrict__ v3) {
    __shared__ __align__(16) char sm[17408];
    const int tid = threadIdx.x;
    const int b2 = blockIdx.x;
    const int half = b2 & 1, ts = b2 >> 1;
    const float* vsrc; const __half* Wg; __half* outv;
    int C, Nv, nb;
    if (ts < 512)      { vsrc = v1; Wg = g_Wvh;         outv = g_val1; C = 64;  Nv = 32768; nb = ts*64; }
    else if (ts < 576) { vsrc = v2; Wg = g_Wvh + 16384; outv = g_val2; C = 128; Nv = 4096;  nb = (ts-512)*64; }
    else               { vsrc = v3; Wg = g_Wvh + 49152; outv = g_val3; C = 256; Nv = 512;   nb = (ts-576)*64; }

    __half* Xt = (__half*)sm;     // [64][18]
    __half* Ds = (__half*)sm;     // reuse: [64][136]

    const int warp = tid >> 5, lane = tid & 31;
    const int grp = lane >> 2, tg = lane & 3;
    const int wbase = warp * 16;
    const int rowbase = half*128 + wbase;

    float acc[8][4];
#pragma unroll
    for (int nt = 0; nt < 8; nt++)
#pragma unroll
        for (int i = 0; i < 4; i++) acc[nt][i] = 0.f;

    const int xk = tid >> 4, xv = (tid & 15) * 4;

    for (int kc = 0; kc < C; kc += 16) {
        float4 x4 = *(const float4*)&vsrc[(size_t)(kc + xk)*Nv + nb + xv];
        Xt[(xv+0)*18 + xk] = __float2half_rn(x4.x);
        Xt[(xv+1)*18 + xk] = __float2half_rn(x4.y);
        Xt[(xv+2)*18 + xk] = __float2half_rn(x4.z);
        Xt[(xv+3)*18 + xk] = __float2half_rn(x4.w);
        __syncthreads();

        const __half* Ar = Wg + (size_t)(rowbase + grp)*C + kc;
        unsigned af0 = *(const unsigned*)(Ar + 2*tg);
        unsigned af1 = *(const unsigned*)(Ar + 8*C + 2*tg);
        unsigned af2 = *(const unsigned*)(Ar + 2*tg + 8);
        unsigned af3 = *(const unsigned*)(Ar + 8*C + 2*tg + 8);
#pragma unroll
        for (int nt = 0; nt < 8; nt++) {
            const __half* Br = Xt + (nt*8 + grp)*18 + 2*tg;
            unsigned b0 = *(const unsigned*)Br;
            unsigned b1 = *(const unsigned*)(Br + 8);
            asm volatile(
                "mma.sync.aligned.m16n8k16.row.col.f32.f16.f16.f32 "
                "{%0,%1,%2,%3}, {%4,%5,%6,%7}, {%8,%9}, {%0,%1,%2,%3};"
                : "+f"(acc[nt][0]), "+f"(acc[nt][1]),
                  "+f"(acc[nt][2]), "+f"(acc[nt][3])
                : "r"(af0), "r"(af1), "r"(af2), "r"(af3),
                  "r"(b0), "r"(b1));
        }
        __syncthreads();
    }

    {
        const int sl = wbase + grp;
#pragma unroll
        for (int nt = 0; nt < 8; nt++) {
            const int vv = nt*8 + 2*tg;
            Ds[vv*136 + sl]         = __float2half_rn(acc[nt][0]);
            Ds[(vv+1)*136 + sl]     = __float2half_rn(acc[nt][1]);
            Ds[vv*136 + sl + 8]     = __float2half_rn(acc[nt][2]);
            Ds[(vv+1)*136 + sl + 8] = __float2half_rn(acc[nt][3]);
        }
    }
    __syncthreads();
    for (int i = tid; i < 1024; i += 256) {
        int v = i >> 4, j = i & 15;
        *reinterpret_cast<uint4*>(&outv[(size_t)(nb + v)*256 + half*128 + j*8]) =
            *reinterpret_cast<const uint4*>(&Ds[v*136 + j*8]);
    }
}

// ---------------- K4: gather, guard-based ----------------
__global__ void __launch_bounds__(512, 3) k4_sample() {
    const int tid = threadIdx.x;
    const int warp = tid >> 5, lane = tid & 31;
    const int gw = blockIdx.x*16 + warp;
    const int h = gw >> 12, n = gw & 4095;
    const int corner = lane >> 2, q8 = (lane & 3) * 8;
    const int cx = corner & 1, cy = (corner >> 1) & 1, cz = corner >> 2;

    float2 acc0[4], acc1[4];
#pragma unroll
    for (int j = 0; j < 4; j++) { acc0[j] = make_float2(0.f,0.f); acc1[j] = make_float2(0.f,0.f); }

    const int ptb = h*16*4096 + n;
    const unsigned short* mdw = reinterpret_cast<const unsigned short*>(g_mdB);

    {
        const int cq = q8 + (cx ? 32 : 0) + (cy ? 64*32 : 0) + (cz ? 64*64*32 : 0);
#pragma unroll
        for (int p = 0; p < 4; p++) {
            int idx = ptb + p*4096;
            int2 A = g_mdA[idx];
            float w = (float)mdw[idx*8 + corner] * __int_as_float(A.y);
            union { uint4 u; __half2 hh[4]; } d;
            d.u = *reinterpret_cast<const uint4*>(g_v0ph + A.x + cq);
#pragma unroll
            for (int j = 0; j < 4; j++) {
                float2 f = __half22float2(d.hh[j]);
                acc0[j].x += w*f.x; acc0[j].y += w*f.y;
            }
        }
    }
#pragma unroll
    for (int s = 1; s < 4; s++) {
        const __half* vptr = (s == 1) ? g_val1 : (s == 2) ? g_val2 : g_val3;
        const int S = 64 >> s;
        const int cq = q8 + (cx ? 256 : 0) + (cy ? S*256 : 0) + (cz ? S*S*256 : 0);
#pragma unroll
        for (int p = 0; p < 4; p++) {
            int idx = ptb + (s*4 + p)*4096;
            int2 A = g_mdA[idx];
            float w = (float)mdw[idx*8 + corner] * __int_as_float(A.y);
            union { uint4 u; __half2 hh[4]; } d;
            d.u = *reinterpret_cast<const uint4*>(vptr + A.x + cq);
#pragma unroll
            for (int j = 0; j < 4; j++) {
                float2 f = __half22float2(d.hh[j]);
                acc1[j].x += w*f.x; acc1[j].y += w*f.y;
            }
        }
    }
#pragma unroll
    for (int m = 4; m <= 16; m <<= 1) {
#pragma unroll
        for (int j = 0; j < 4; j++) {
            acc0[j].x += __shfl_xor_sync(FULL, acc0[j].x, m);
            acc0[j].y += __shfl_xor_sync(FULL, acc0[j].y, m);
            acc1[j].x += __shfl_xor_sync(FULL, acc1[j].x, m);
            acc1[j].y += __shfl_xor_sync(FULL, acc1[j].y, m);
        }
    }
    if (lane < 4) {
        const int base = n*256 + h*32 + q8;
        *(float4*)&g_accA[base]     = make_float4(acc0[0].x, acc0[0].y, acc0[1].x, acc0[1].y);
        *(float4*)&g_accA[base + 4] = make_float4(acc0[2].x, acc0[2].y, acc0[3].x, acc0[3].y);
        *(float4*)&g_accB[base]     = make_float4(acc1[0].x, acc1[0].y, acc1[1].x, acc1[1].y);
        *(float4*)&g_accB[base + 4] = make_float4(acc1[2].x, acc1[2].y, acc1[3].x, acc1[3].y);
    }
}

// ---------------- K5: output GEMM [128][512] @ [512][4096], N-tile 16, grid 256 ----------------
#define K5PX2 20
#define K5PW 132
__global__ void __launch_bounds__(256) k5_out() {
    __shared__ __align__(16) float xs[32*K5PX2];
    __shared__ __align__(16) float sW[32*K5PW];
    const int tid = threadIdx.x;
    const int nb = blockIdx.x * 16;
    const int rg = tid >> 3, cg = tid & 7;   // 32 rowgroups x 4 rows, 8 colgroups x 2 vox
    const int rbase = rg * 4, vbase = cg * 2;

    unsigned long long acc2[4];
#pragma unroll
    for (int i = 0; i < 4; i++) acc2[i] = 0ull;

    for (int kc = 0; kc < 512; kc += 32) {
        __syncthreads();
        if (tid < 128) {
            const float* srcbuf = (kc < 256) ? g_accA : g_accB;
            const int ko = kc & 255;
            const int v = tid & 15, kq = tid >> 4;  // 8 k-quads
            float4 x4 = *(const float4*)&srcbuf[(nb + v)*256 + ko + kq*4];
            xs[(kq*4+0)*K5PX2 + v] = x4.x;
            xs[(kq*4+1)*K5PX2 + v] = x4.y;
            xs[(kq*4+2)*K5PX2 + v] = x4.z;
            xs[(kq*4+3)*K5PX2 + v] = x4.w;
        }
        for (int e = tid; e < 32*32; e += 256) {
            int k = e >> 5, c4 = e & 31;
            *(float4*)&sW[k*K5PW + c4*4] = *(const float4*)&g_WcombT[(kc + k)*128 + c4*4];
        }
        __syncthreads();
#pragma unroll
        for (int k = 0; k < 32; k++) {
            float4 wa = *(const float4*)&sW[k*K5PW + rbase];
            float w[4] = {wa.x, wa.y, wa.z, wa.w};
            unsigned long long xv = *(const unsigned long long*)&xs[k*K5PX2 + vbase];
#pragma unroll
            for (int i = 0; i < 4; i++) {
                unsigned long long wp = pack2(w[i], w[i]);
                fma2(acc2[i], wp, xv);
            }
        }
    }
#pragma unroll
    for (int i = 0; i < 4; i++) {
        float2 f = u2f(acc2[i]);
        *(float2*)&g_outbuf[(rbase + i)*4096 + nb + vbase] = f;
    }
}

// ---------------- K6: InstanceNorm per channel ----------------
__global__ void __launch_bounds__(256) k6_norm(const float* __restrict__ gamma,
                                               const float* __restrict__ beta,
                                               float* __restrict__ out) {
    const int c = blockIdx.x, tid = threadIdx.x;
    const float* row = &g_outbuf[c*4096];
    float s = 0.f, s2 = 0.f;
    for (int i = tid; i < 4096; i += 256) { float x = row[i]; s += x; s2 += x*x; }
#pragma unroll
    for (int m = 16; m > 0; m >>= 1) {
        s  += __shfl_xor_sync(FULL, s,  m);
        s2 += __shfl_xor_sync(FULL, s2, m);
    }
    __shared__ float rs[8], rq[8];
    __shared__ float smu, srstd;
    if ((tid & 31) == 0) { rs[tid >> 5] = s; rq[tid >> 5] = s2; }
    __syncthreads();
    if (tid == 0) {
        float ts = 0.f, tq = 0.f;
        for (int i = 0; i < 8; i++) { ts += rs[i]; tq += rq[i]; }
        float mu = ts * (1.f/4096.f);
        smu = mu;
        srstd = rsqrtf(tq * (1.f/4096.f) - mu*mu + 1e-5f);
    }
    __syncthreads();
    const float g = gamma[c] * srstd, b = beta[c], mu = smu;
    for (int i = tid; i < 4096; i += 256)
        out[c*4096 + i] = (row[i] - mu) * g + b;
}

// ---------------- launch ----------------
extern "C" void kernel_launch(void* const* d_in, const int* in_sizes, int n_in,
                              void* d_out, int out_size) {
    const float* qf    = (const float*)d_in[0];
    const float* v0    = (const float*)d_in[1];
    const float* v1    = (const float*)d_in[2];
    const float* v2    = (const float*)d_in[3];
    const float* v3    = (const float*)d_in[4];
    const float* Wq    = (const float*)d_in[5];
    const float* Wv0   = (const float*)d_in[6];
    const float* Wv1   = (const float*)d_in[7];
    const float* Wv2   = (const float*)d_in[8];
    const float* Wv3   = (const float*)d_in[9];
    const float* Woff  = (const float*)d_in[10];
    const float* boff  = (const float*)d_in[11];
    const float* Wwt   = (const float*)d_in[12];
    const float* bwt   = (const float*)d_in[13];
    const float* Wout  = (const float*)d_in[14];
    const float* gamma = (const float*)d_in[15];
    const float* beta  = (const float*)d_in[16];
    float* out = (float*)d_out;

    // Lazily-created side streams + events (graph capture turns the event
    // record/wait pattern into fork/join edges).
    static cudaStream_t sB = nullptr, sC = nullptr;
    static cudaEvent_t  evFork = nullptr, evB = nullptr, evC = nullptr;
    static bool s_ok = false;
    if (!sB) {
        bool ok = (cudaStreamCreateWithFlags(&sB, cudaStreamNonBlocking) == cudaSuccess);
        ok = ok && (cudaStreamCreateWithFlags(&sC, cudaStreamNonBlocking) == cudaSuccess);
        ok = ok && (cudaEventCreateWithFlags(&evFork, cudaEventDisableTiming) == cudaSuccess);
        ok = ok && (cudaEventCreateWithFlags(&evB, cudaEventDisableTiming) == cudaSuccess);
        ok = ok && (cudaEventCreateWithFlags(&evC, cudaEventDisableTiming) == cudaSuccess);
        s_ok = ok;
    }

    if (s_ok) {
        cudaEventRecord(evFork, 0);
        cudaStreamWaitEvent(sB, evFork, 0);
        cudaStreamWaitEvent(sC, evFork, 0);

        // main: k0a -> k1 (offsets/weights path)
        k0a_fold<<<640, 128>>>(Woff, Wwt, Wq, boff, bwt, Wout, Wv0);
        // side B: k0b -> k3 (value projections)
        k0b_wvh<<<64, 128, 0, sB>>>(Wv1, Wv2, Wv3);
        // side C: k2 (v0 transpose)
        k2_packv0<<<2048, 256, 0, sC>>>(v0);
        cudaEventRecord(evC, sC);
        k3_proj<<<1168, 256, 0, sB>>>(v1, v2, v3);
        cudaEventRecord(evB, sB);

        k1_offaw<<<256, 256>>>(qf);

        // join: k4 reads md (main), g_val* (B), g_v0ph (C)
        cudaStreamWaitEvent(0, evB, 0);
        cudaStreamWaitEvent(0, evC, 0);
        k4_sample<<<2048, 512>>>();
        k5_out<<<256, 256>>>();
        k6_norm<<<128, 256>>>(gamma, beta, out);
    } else {
        k0a_fold<<<640, 128>>>(Woff, Wwt, Wq, boff, bwt, Wout, Wv0);
        k0b_wvh<<<64, 128>>>(Wv1, Wv2, Wv3);
        k2_packv0<<<2048, 256>>>(v0);
        k3_proj<<<1168, 256>>>(v1, v2, v3);
        k1_offaw<<<256, 256>>>(qf);
        k4_sample<<<2048, 512>>>();
        k5_out<<<256, 256>>>();
        k6_norm<<<128, 256>>>(gamma, beta, out);
    }
}

// round 17
// speedup vs baseline: 1.2833x; 1.0243x over previous
#include <cuda_runtime.h>
#include <cuda_fp16.h>
#include <math.h>

#define FULL 0xffffffffu

// ---------------- f32x2 packed-FMA helpers ----------------
__device__ __forceinline__ unsigned long long pack2(float a, float b) {
    unsigned long long r;
    asm("mov.b64 %0, {%1, %2};" : "=l"(r) : "f"(a), "f"(b));
    return r;
}
__device__ __forceinline__ float2 u2f(unsigned long long v) {
    float2 r;
    asm("mov.b64 {%0, %1}, %2;" : "=f"(r.x), "=f"(r.y) : "l"(v));
    return r;
}
__device__ __forceinline__ void fma2(unsigned long long& d, unsigned long long a, unsigned long long b) {
    asm("fma.rn.f32x2 %0, %1, %2, %0;" : "+l"(d) : "l"(a), "l"(b));
}
__device__ __forceinline__ float tanh_fast(float x) {
    float e = __expf(2.f * x);
    return (e - 1.f) / (e + 1.f);
}

// ---------------- scratch ----------------
// Value buffers carry zero-initialized guard tails so clamped (zero-weight)
// corner reads past the logical end stay finite.
__device__ __align__(16) float  g_W512[512*128];
__device__ float                g_b512[512];
__device__ __align__(16) float  g_WcombT[512*128];
__device__ __align__(16) __half g_Wvh[114688];
__device__ __align__(16) int2   g_mdA[524288];     // per point: {base, aw/65535}
__device__ __align__(16) uint4  g_mdB[524288];     // per point: 8x u16 corner products
__device__ __align__(16) __half g_v0ph[262144*32 + 140000];
__device__ __align__(16) __half g_val1[32768*256 + 272000];
__device__ __align__(16) __half g_val2[4096*256 + 70600];
__device__ __align__(16) __half g_val3[512*256 + 19200];
__device__ __align__(16) float  g_accA[4096*256];
__device__ __align__(16) float  g_accB[4096*256];
__device__ __align__(16) float  g_outbuf[128*4096];

// ---------------- K0a: fold W512 + build WcombT ----------------
__global__ void k0a_fold(const float* __restrict__ Woff, const float* __restrict__ Wwt,
                         const float* __restrict__ Wq,
                         const float* __restrict__ boff, const float* __restrict__ bwt,
                         const float* __restrict__ Wout, const float* __restrict__ Wv0) {
    const int b = blockIdx.x;
    const int t = threadIdx.x;
    if (b < 512) {
        const int j = b;
        const float* A = (j < 384) ? (Woff + j*192) : (Wwt + (j-384)*192);
        float s = 0.f;
        for (int m = 0; m < 192; m++) s += A[m] * Wq[m*128 + t];
        g_W512[j*128 + t] = s;
        if (t == 0) g_b512[j] = (j < 384) ? boff[j] : bwt[j-384];
    } else {
        const int c = b - 512;
#pragma unroll
        for (int kk = 0; kk < 4; kk++) {
            int k = t + kk*128;
            float s;
            if (k < 256) {
                int h = k >> 5, q = k & 31;
                s = 0.f;
                for (int j = 0; j < 24; j++)
                    s += Wout[c*192 + h*24 + j] * Wv0[(h*24 + j)*32 + q];
            } else {
                int k2 = k - 256;
                int h = k2 >> 5, j = k2 & 31;
                s = (j < 24) ? Wout[c*192 + h*24 + j] : 0.f;
            }
            g_WcombT[k*128 + c] = s;
        }
    }
}

// ---------------- K0b: build fp16 value weights ----------------
__global__ void k0b_wvh(const float* __restrict__ Wv1, const float* __restrict__ Wv2,
                        const float* __restrict__ Wv3) {
    int i = blockIdx.x*128 + threadIdx.x;
    for (int idx = i; idx < 114688; idx += 8192) {
        int row, k, C;
        const float* W;
        if (idx < 16384)      { row = idx >> 6;  k = idx & 63;  C = 64;  W = Wv1; }
        else if (idx < 49152) { int d = idx - 16384; row = d >> 7; k = d & 127; C = 128; W = Wv2; }
        else                  { int d = idx - 49152; row = d >> 8; k = d & 255; C = 256; W = Wv3; }
        int h = row >> 5, j = row & 31;
        float v = (j < 24) ? W[(h*24 + j)*C + k] : 0.f;
        g_Wvh[idx] = __float2half_rn(v);
    }
}

// ---------------- K2: transpose v0 -> fp16 [voxel][32] ----------------
__global__ void __launch_bounds__(256) k2_packv0(const float* __restrict__ v0) {
    __shared__ float t[32*129];
    const int vb = blockIdx.x * 128;
    const int tid = threadIdx.x;
    for (int e = tid; e < 32*128; e += 256) {
        int c = e >> 7, v = e & 127;
        t[c*129 + v] = v0[c*262144 + vb + v];
    }
    __syncthreads();
    for (int e = tid; e < 512; e += 256) {
        int v = e >> 2, q = e & 3;
        union { uint4 u; __half2 h[4]; } o;
#pragma unroll
        for (int j = 0; j < 4; j++)
            o.h[j] = __floats2half2_rn(t[(q*8 + 2*j)*129 + v], t[(q*8 + 2*j + 1)*129 + v]);
        *reinterpret_cast<uint4*>(&g_v0ph[(vb + v)*32 + q*8]) = o.u;
    }
}

// ---------------- K1: half-row-split 256x128 GEMM per block + epilogue ----------------
// grid 512: tile = b>>1 (16 voxels), half = b&1 (head group 0..3 or 4..7).
// Row set: half==0 -> rows {0..191, 384..447}; half==1 -> {192..383, 448..511}.
#define K1PX 20
#define K1PW2 260
__global__ void __launch_bounds__(256) k1_offaw(const float* __restrict__ qf) {
    __shared__ __align__(16) char sm1[26880];
    float* xs   = (float*)sm1;            // [128][20] = 10240B
    float* sW   = (float*)(sm1 + 10240);  // [16][260] = 16640B
    float* sbuf = (float*)sm1;            // reuse: [256][20] = 20480B

    const int tid = threadIdx.x;
    const int half = blockIdx.x & 1;
    const int nb = (blockIdx.x >> 1) * 16;
    const int rg = tid >> 2, cg = tid & 3;
    const int rbase = rg * 4, vbase = cg * 4;

    for (int e = tid; e < 128*16; e += 256) {
        int k = e >> 4, v = e & 15;
        xs[k*K1PX + v] = qf[k*4096 + nb + v];
    }
    unsigned long long acc2[4][2];
#pragma unroll
    for (int i = 0; i < 4; i++) {
        int r = rbase + i;
        int grow = (r < 192) ? half*192 + r : 448 - 64*(1-half) + (r - 192);
        float bv = g_b512[grow];
        acc2[i][0] = pack2(bv, bv);
        acc2[i][1] = acc2[i][0];
    }

    for (int kc = 0; kc < 128; kc += 16) {
        __syncthreads();
        for (int e = tid; e < 256*4; e += 256) {
            int r = e >> 2, k4 = e & 3;
            int grow = (r < 192) ? half*192 + r : 448 - 64*(1-half) + (r - 192);
            float4 w4 = *(const float4*)&g_W512[grow*128 + kc + k4*4];
            sW[(k4*4+0)*K1PW2 + r] = w4.x;
            sW[(k4*4+1)*K1PW2 + r] = w4.y;
            sW[(k4*4+2)*K1PW2 + r] = w4.z;
            sW[(k4*4+3)*K1PW2 + r] = w4.w;
        }
        __syncthreads();
#pragma unroll
        for (int k = 0; k < 16; k++) {
            float4 wa = *(const float4*)&sW[k*K1PW2 + rbase];
            float w[4] = {wa.x, wa.y, wa.z, wa.w};
            ulonglong2 xv = *(const ulonglong2*)&xs[(kc + k)*K1PX + vbase];
#pragma unroll
            for (int i = 0; i < 4; i++) {
                unsigned long long wp = pack2(w[i], w[i]);
                fma2(acc2[i][0], wp, xv.x);
                fma2(acc2[i][1], wp, xv.y);
            }
        }
    }
    __syncthreads();
#pragma unroll
    for (int i = 0; i < 4; i++) {
        float2 lo = u2f(acc2[i][0]), hi = u2f(acc2[i][1]);
        *(float4*)&sbuf[(rbase + i)*K1PX + vbase] = make_float4(lo.x, lo.y, hi.x, hi.y);
    }
    __syncthreads();

    // epilogue: 64 units (hl,v) x 4 threads (one scale each)
    const int u = tid >> 2;
    const int hl = u >> 4, v = u & 15;
    const int s = tid & 3;
    const int h = half*4 + hl;
    const int n = nb + v;
    const int wq = n & 15, hq = (n >> 4) & 15, dq = n >> 8;
    const float bgx = -1.f + (float)wq * (2.f/15.f);
    const float bgy = -1.f + (float)hq * (2.f/15.f);
    const float bgz = -1.f + (float)dq * (2.f/15.f);
    float e[16];
    float m = -1e30f;
#pragma unroll
    for (int j = 0; j < 16; j++) {
        e[j] = sbuf[(192 + hl*16 + j)*K1PX + v];
        m = fmaxf(m, e[j]);
    }
    float sum = 0.f;
#pragma unroll
    for (int j = 0; j < 16; j++) { e[j] = __expf(e[j] - m); sum += e[j]; }
    const float inv = 1.f / sum;

    const int S = 64 >> s;
    const float fS = (float)S;
    const int stride = (s == 0) ? 32 : 256;
    const int hofs = (s == 0) ? 0 : h*32;
#pragma unroll
    for (int p = 0; p < 4; p++) {
        const int rb = (hl*16 + s*4 + p) * 3;   // local offset rows
        float gx = bgx + tanh_fast(sbuf[(rb+0)*K1PX + v]) * 0.35f;
        float gy = bgy + tanh_fast(sbuf[(rb+1)*K1PX + v]) * 0.35f;
        float gz = bgz + tanh_fast(sbuf[(rb+2)*K1PX + v]) * 0.35f;
        float ix = fminf(fmaxf(((gx + 1.f)*fS - 1.f)*0.5f, 0.f), fS - 1.f);
        float iy = fminf(fmaxf(((gy + 1.f)*fS - 1.f)*0.5f, 0.f), fS - 1.f);
        float iz = fminf(fmaxf(((gz + 1.f)*fS - 1.f)*0.5f, 0.f), fS - 1.f);
        float x0f = floorf(ix), y0f = floorf(iy), z0f = floorf(iz);
        float wx = ix - x0f, wy = iy - y0f, wz = iz - z0f;
        int x0 = (int)x0f, y0 = (int)y0f, z0 = (int)z0f;
        int base = ((z0*S + y0)*S + x0)*stride + hofs;
        float aw = e[s*4 + p] * inv;
        float wx1 = 1.f - wx, wy1 = 1.f - wy, wz1 = 1.f - wz;
        float p00 = wz1*wy1, p01 = wz1*wy, p10 = wz*wy1, p11 = wz*wy;
        unsigned u0 = (unsigned)(p00*wx1*65535.f + 0.5f);
        unsigned u1 = (unsigned)(p00*wx *65535.f + 0.5f);
        unsigned u2 = (unsigned)(p01*wx1*65535.f + 0.5f);
        unsigned u3 = (unsigned)(p01*wx *65535.f + 0.5f);
        unsigned u4 = (unsigned)(p10*wx1*65535.f + 0.5f);
        unsigned u5 = (unsigned)(p10*wx *65535.f + 0.5f);
        unsigned u6 = (unsigned)(p11*wx1*65535.f + 0.5f);
        unsigned u7 = (unsigned)(p11*wx *65535.f + 0.5f);
        uint4 B = make_uint4((u1<<16)|u0, (u3<<16)|u2, (u5<<16)|u4, (u7<<16)|u6);
        int2 A = make_int2(base, __float_as_int(aw * (1.f/65535.f)));
        int idx = (h*16 + s*4 + p)*4096 + n;
        g_mdA[idx] = A;
        g_mdB[idx] = B;
    }
}

// ---------------- K3: HMMA projections, half-tile per block, double-buffered X ----------------
__global__ void __launch_bounds__(256) k3_proj(const float* __restrict__ v1,
                                               const float* __restrict__ v2,
                                               const float* __restrict__ v3) {
    __shared__ __align__(16) char sm[17408];
    const int tid = threadIdx.x;
    const int b2 = blockIdx.x;
    const int half = b2 & 1, ts = b2 >> 1;
    const float* vsrc; const __half* Wg; __half* outv;
    int C, Nv, nb;
    if (ts < 512)      { vsrc = v1; Wg = g_Wvh;         outv = g_val1; C = 64;  Nv = 32768; nb = ts*64; }
    else if (ts < 576) { vsrc = v2; Wg = g_Wvh + 16384; outv = g_val2; C = 128; Nv = 4096;  nb = (ts-512)*64; }
    else               { vsrc = v3; Wg = g_Wvh + 49152; outv = g_val3; C = 256; Nv = 512;   nb = (ts-576)*64; }

    __half* Xt = (__half*)sm;     // two buffers [2][64*18]
    __half* Ds = (__half*)sm;     // reuse after loop: [64][136]

    const int warp = tid >> 5, lane = tid & 31;
    const int grp = lane >> 2, tg = lane & 3;
    const int wbase = warp * 16;
    const int rowbase = half*128 + wbase;

    float acc[8][4];
#pragma unroll
    for (int nt = 0; nt < 8; nt++)
#pragma unroll
        for (int i = 0; i < 4; i++) acc[nt][i] = 0.f;

    const int xk = tid >> 4, xv = (tid & 15) * 4;
    const int nIter = C >> 4;

    // prologue: stage chunk 0 into buffer 0
    {
        float4 x4 = *(const float4*)&vsrc[(size_t)xk*Nv + nb + xv];
        Xt[(xv+0)*18 + xk] = __float2half_rn(x4.x);
        Xt[(xv+1)*18 + xk] = __float2half_rn(x4.y);
        Xt[(xv+2)*18 + xk] = __float2half_rn(x4.z);
        Xt[(xv+3)*18 + xk] = __float2half_rn(x4.w);
    }
    __syncthreads();

    for (int i = 0; i < nIter; i++) {
        const int cur = i & 1;
        const bool hasNext = (i + 1 < nIter);
        float4 xn;
        if (hasNext)
            xn = *(const float4*)&vsrc[(size_t)((i+1)*16 + xk)*Nv + nb + xv];

        const __half* Ar = Wg + (size_t)(rowbase + grp)*C + i*16;
        unsigned af0 = *(const unsigned*)(Ar + 2*tg);
        unsigned af1 = *(const unsigned*)(Ar + 8*C + 2*tg);
        unsigned af2 = *(const unsigned*)(Ar + 2*tg + 8);
        unsigned af3 = *(const unsigned*)(Ar + 8*C + 2*tg + 8);
        const __half* Xc = Xt + cur*1152;
#pragma unroll
        for (int nt = 0; nt < 8; nt++) {
            const __half* Br = Xc + (nt*8 + grp)*18 + 2*tg;
            unsigned b0 = *(const unsigned*)Br;
            unsigned b1 = *(const unsigned*)(Br + 8);
            asm volatile(
                "mma.sync.aligned.m16n8k16.row.col.f32.f16.f16.f32 "
                "{%0,%1,%2,%3}, {%4,%5,%6,%7}, {%8,%9}, {%0,%1,%2,%3};"
                : "+f"(acc[nt][0]), "+f"(acc[nt][1]),
                  "+f"(acc[nt][2]), "+f"(acc[nt][3])
                : "r"(af0), "r"(af1), "r"(af2), "r"(af3),
                  "r"(b0), "r"(b1));
        }
        if (hasNext) {
            __half* Xn = Xt + (cur^1)*1152;
            Xn[(xv+0)*18 + xk] = __float2half_rn(xn.x);
            Xn[(xv+1)*18 + xk] = __float2half_rn(xn.y);
            Xn[(xv+2)*18 + xk] = __float2half_rn(xn.z);
            Xn[(xv+3)*18 + xk] = __float2half_rn(xn.w);
        }
        __syncthreads();
    }

    {
        const int sl = wbase + grp;
#pragma unroll
        for (int nt = 0; nt < 8; nt++) {
            const int vv = nt*8 + 2*tg;
            Ds[vv*136 + sl]         = __float2half_rn(acc[nt][0]);
            Ds[(vv+1)*136 + sl]     = __float2half_rn(acc[nt][1]);
            Ds[vv*136 + sl + 8]     = __float2half_rn(acc[nt][2]);
            Ds[(vv+1)*136 + sl + 8] = __float2half_rn(acc[nt][3]);
        }
    }
    __syncthreads();
    for (int i = tid; i < 1024; i += 256) {
        int v = i >> 4, j = i & 15;
        *reinterpret_cast<uint4*>(&outv[(size_t)(nb + v)*256 + half*128 + j*8]) =
            *reinterpret_cast<const uint4*>(&Ds[v*136 + j*8]);
    }
}

// ---------------- K4: gather, guard-based ----------------
__global__ void __launch_bounds__(512, 3) k4_sample() {
    const int tid = threadIdx.x;
    const int warp = tid >> 5, lane = tid & 31;
    const int gw = blockIdx.x*16 + warp;
    const int h = gw >> 12, n = gw & 4095;
    const int corner = lane >> 2, q8 = (lane & 3) * 8;
    const int cx = corner & 1, cy = (corner >> 1) & 1, cz = corner >> 2;

    float2 acc0[4], acc1[4];
#pragma unroll
    for (int j = 0; j < 4; j++) { acc0[j] = make_float2(0.f,0.f); acc1[j] = make_float2(0.f,0.f); }

    const int ptb = h*16*4096 + n;
    const unsigned short* mdw = reinterpret_cast<const unsigned short*>(g_mdB);

    {
        const int cq = q8 + (cx ? 32 : 0) + (cy ? 64*32 : 0) + (cz ? 64*64*32 : 0);
#pragma unroll
        for (int p = 0; p < 4; p++) {
            int idx = ptb + p*4096;
            int2 A = g_mdA[idx];
            float w = (float)mdw[idx*8 + corner] * __int_as_float(A.y);
            union { uint4 u; __half2 hh[4]; } d;
            d.u = *reinterpret_cast<const uint4*>(g_v0ph + A.x + cq);
#pragma unroll
            for (int j = 0; j < 4; j++) {
                float2 f = __half22float2(d.hh[j]);
                acc0[j].x += w*f.x; acc0[j].y += w*f.y;
            }
        }
    }
#pragma unroll
    for (int s = 1; s < 4; s++) {
        const __half* vptr = (s == 1) ? g_val1 : (s == 2) ? g_val2 : g_val3;
        const int S = 64 >> s;
        const int cq = q8 + (cx ? 256 : 0) + (cy ? S*256 : 0) + (cz ? S*S*256 : 0);
#pragma unroll
        for (int p = 0; p < 4; p++) {
            int idx = ptb + (s*4 + p)*4096;
            int2 A = g_mdA[idx];
            float w = (float)mdw[idx*8 + corner] * __int_as_float(A.y);
            union { uint4 u; __half2 hh[4]; } d;
            d.u = *reinterpret_cast<const uint4*>(vptr + A.x + cq);
#pragma unroll
            for (int j = 0; j < 4; j++) {
                float2 f = __half22float2(d.hh[j]);
                acc1[j].x += w*f.x; acc1[j].y += w*f.y;
            }
        }
    }
#pragma unroll
    for (int m = 4; m <= 16; m <<= 1) {
#pragma unroll
        for (int j = 0; j < 4; j++) {
            acc0[j].x += __shfl_xor_sync(FULL, acc0[j].x, m);
            acc0[j].y += __shfl_xor_sync(FULL, acc0[j].y, m);
            acc1[j].x += __shfl_xor_sync(FULL, acc1[j].x, m);
            acc1[j].y += __shfl_xor_sync(FULL, acc1[j].y, m);
        }
    }
    if (lane < 4) {
        const int base = n*256 + h*32 + q8;
        *(float4*)&g_accA[base]     = make_float4(acc0[0].x, acc0[0].y, acc0[1].x, acc0[1].y);
        *(float4*)&g_accA[base + 4] = make_float4(acc0[2].x, acc0[2].y, acc0[3].x, acc0[3].y);
        *(float4*)&g_accB[base]     = make_float4(acc1[0].x, acc1[0].y, acc1[1].x, acc1[1].y);
        *(float4*)&g_accB[base + 4] = make_float4(acc1[2].x, acc1[2].y, acc1[3].x, acc1[3].y);
    }
}

// ---------------- K5: output GEMM [128][512] @ [512][4096], N-tile 16, grid 256 ----------------
#define K5PX2 20
#define K5PW 132
__global__ void __launch_bounds__(256) k5_out() {
    __shared__ __align__(16) float xs[32*K5PX2];
    __shared__ __align__(16) float sW[32*K5PW];
    const int tid = threadIdx.x;
    const int nb = blockIdx.x * 16;
    const int rg = tid >> 3, cg = tid & 7;
    const int rbase = rg * 4, vbase = cg * 2;

    unsigned long long acc2[4];
#pragma unroll
    for (int i = 0; i < 4; i++) acc2[i] = 0ull;

    for (int kc = 0; kc < 512; kc += 32) {
        __syncthreads();
        if (tid < 128) {
            const float* srcbuf = (kc < 256) ? g_accA : g_accB;
            const int ko = kc & 255;
            const int v = tid & 15, kq = tid >> 4;
            float4 x4 = *(const float4*)&srcbuf[(nb + v)*256 + ko + kq*4];
            xs[(kq*4+0)*K5PX2 + v] = x4.x;
            xs[(kq*4+1)*K5PX2 + v] = x4.y;
            xs[(kq*4+2)*K5PX2 + v] = x4.z;
            xs[(kq*4+3)*K5PX2 + v] = x4.w;
        }
        for (int e = tid; e < 32*32; e += 256) {
            int k = e >> 5, c4 = e & 31;
            *(float4*)&sW[k*K5PW + c4*4] = *(const float4*)&g_WcombT[(kc + k)*128 + c4*4];
        }
        __syncthreads();
#pragma unroll
        for (int k = 0; k < 32; k++) {
            float4 wa = *(const float4*)&sW[k*K5PW + rbase];
            float w[4] = {wa.x, wa.y, wa.z, wa.w};
            unsigned long long xv = *(const unsigned long long*)&xs[k*K5PX2 + vbase];
#pragma unroll
            for (int i = 0; i < 4; i++) {
                unsigned long long wp = pack2(w[i], w[i]);
                fma2(acc2[i], wp, xv);
            }
        }
    }
#pragma unroll
    for (int i = 0; i < 4; i++) {
        float2 f = u2f(acc2[i]);
        *(float2*)&g_outbuf[(rbase + i)*4096 + nb + vbase] = f;
    }
}

// ---------------- K6: InstanceNorm per channel ----------------
__global__ void __launch_bounds__(256) k6_norm(const float* __restrict__ gamma,
                                               const float* __restrict__ beta,
                                               float* __restrict__ out) {
    const int c = blockIdx.x, tid = threadIdx.x;
    const float* row = &g_outbuf[c*4096];
    float s = 0.f, s2 = 0.f;
    for (int i = tid; i < 4096; i += 256) { float x = row[i]; s += x; s2 += x*x; }
#pragma unroll
    for (int m = 16; m > 0; m >>= 1) {
        s  += __shfl_xor_sync(FULL, s,  m);
        s2 += __shfl_xor_sync(FULL, s2, m);
    }
    __shared__ float rs[8], rq[8];
    __shared__ float smu, srstd;
    if ((tid & 31) == 0) { rs[tid >> 5] = s; rq[tid >> 5] = s2; }
    __syncthreads();
    if (tid == 0) {
        float ts = 0.f, tq = 0.f;
        for (int i = 0; i < 8; i++) { ts += rs[i]; tq += rq[i]; }
        float mu = ts * (1.f/4096.f);
        smu = mu;
        srstd = rsqrtf(tq * (1.f/4096.f) - mu*mu + 1e-5f);
    }
    __syncthreads();
    const float g = gamma[c] * srstd, b = beta[c], mu = smu;
    for (int i = tid; i < 4096; i += 256)
        out[c*4096 + i] = (row[i] - mu) * g + b;
}

// ---------------- launch ----------------
extern "C" void kernel_launch(void* const* d_in, const int* in_sizes, int n_in,
                              void* d_out, int out_size) {
    const float* qf    = (const float*)d_in[0];
    const float* v0    = (const float*)d_in[1];
    const float* v1    = (const float*)d_in[2];
    const float* v2    = (const float*)d_in[3];
    const float* v3    = (const float*)d_in[4];
    const float* Wq    = (const float*)d_in[5];
    const float* Wv0   = (const float*)d_in[6];
    const float* Wv1   = (const float*)d_in[7];
    const float* Wv2   = (const float*)d_in[8];
    const float* Wv3   = (const float*)d_in[9];
    const float* Woff  = (const float*)d_in[10];
    const float* boff  = (const float*)d_in[11];
    const float* Wwt   = (const float*)d_in[12];
    const float* bwt   = (const float*)d_in[13];
    const float* Wout  = (const float*)d_in[14];
    const float* gamma = (const float*)d_in[15];
    const float* beta  = (const float*)d_in[16];
    float* out = (float*)d_out;

    static cudaStream_t sB = nullptr, sC = nullptr;
    static cudaEvent_t  evFork = nullptr, evB = nullptr, evC = nullptr;
    static bool s_ok = false;
    if (!sB) {
        bool ok = (cudaStreamCreateWithFlags(&sB, cudaStreamNonBlocking) == cudaSuccess);
        ok = ok && (cudaStreamCreateWithFlags(&sC, cudaStreamNonBlocking) == cudaSuccess);
        ok = ok && (cudaEventCreateWithFlags(&evFork, cudaEventDisableTiming) == cudaSuccess);
        ok = ok && (cudaEventCreateWithFlags(&evB, cudaEventDisableTiming) == cudaSuccess);
        ok = ok && (cudaEventCreateWithFlags(&evC, cudaEventDisableTiming) == cudaSuccess);
        s_ok = ok;
    }

    if (s_ok) {
        cudaEventRecord(evFork, 0);
        cudaStreamWaitEvent(sB, evFork, 0);
        cudaStreamWaitEvent(sC, evFork, 0);

        k0a_fold<<<640, 128>>>(Woff, Wwt, Wq, boff, bwt, Wout, Wv0);       // 1
        k0b_wvh<<<64, 128, 0, sB>>>(Wv1, Wv2, Wv3);                        // 2
        k2_packv0<<<2048, 256, 0, sC>>>(v0);                               // 3
        cudaEventRecord(evC, sC);
        k1_offaw<<<512, 256>>>(qf);                                        // 4 (ncu slot)
        k3_proj<<<1168, 256, 0, sB>>>(v1, v2, v3);                         // 5
        cudaEventRecord(evB, sB);

        cudaStreamWaitEvent(0, evB, 0);
        cudaStreamWaitEvent(0, evC, 0);
        k4_sample<<<2048, 512>>>();
        k5_out<<<256, 256>>>();
        k6_norm<<<128, 256>>>(gamma, beta, out);
    } else {
        k0a_fold<<<640, 128>>>(Woff, Wwt, Wq, boff, bwt, Wout, Wv0);
        k0b_wvh<<<64, 128>>>(Wv1, Wv2, Wv3);
        k2_packv0<<<2048, 256>>>(v0);
        k1_offaw<<<512, 256>>>(qf);
        k3_proj<<<1168, 256>>>(v1, v2, v3);
        k4_sample<<<2048, 512>>>();
        k5_out<<<256, 256>>>();
        k6_norm<<<128, 256>>>(gamma, beta, out);
    }
}